// round 11
// baseline (speedup 1.0000x reference)
#include <cuda_runtime.h>
#include <cuda_fp16.h>
#include <math.h>
#include <stdint.h>

#define NN 50000
#define NE 100000
#define NRL 500
#define NB 64
#define FF 768
#define FV 2304
#define NMEGA (4 * FF)  // 3072
#define ENC_NEG_INF 0x007FFFFFu

// ---------------- scratch (static device memory; no allocations) ------------
__device__ __align__(16) __half g_h0[NN * FF];    // hl (fp16, GEMM out)
__device__ __align__(16) __half g_h1[NN * FF];    // hs (fp16, GEMM out)
__device__ __align__(16) __half g_h2[NN * FF];    // t1 (fp16, GEMM out)
__device__ __align__(16) __half g_h3[NN * FF];    // t2 (fp16, GEMM out)
__device__ __align__(16) float g_big0[NN * FF];   // gl (fp32)
__device__ __align__(16) float g_big1[NN * FF];   // gr (fp32)
__device__ __align__(16) float g_big2[NN * FF];   // msg accum / ent_emb
__device__ __align__(16) __half g_Ahf[NN * FF];   // fp16 entities
__device__ __align__(16) __half g_Bhf[NMEGA * FF];  // [3072,768] fused W^T fp16
__device__ __align__(16) float g_P[2 * FF * FF];  // P1 | P2
__device__ __align__(16) float g_q3[3 * NB * FF];  // hq | Gql | Gqr
__device__ __align__(16) float g_ge[NRL * FF];
__device__ float g_logit[NE];
__device__ unsigned g_nmax[NN];
__device__ float g_nsum[NN];
__device__ float g_gate[NN];
__device__ unsigned g_gmax[NB];
__device__ float g_gsum[NB];
__device__ __align__(16) float g_pool[NB * FF];

// ---------------- helpers ----------------------------------------------------
__device__ __forceinline__ float lrelu(float x) { return x > 0.f ? x : 0.2f * x; }

__device__ __forceinline__ unsigned f2ord(float f) {
    unsigned u = __float_as_uint(f);
    return (u & 0x80000000u) ? ~u : (u | 0x80000000u);
}
__device__ __forceinline__ float ord2f(unsigned u) {
    return (u & 0x80000000u) ? __uint_as_float(u & 0x7FFFFFFFu) : __uint_as_float(~u);
}

__device__ __forceinline__ unsigned cat_h(__half a, __half b) {
    return (unsigned)__half_as_ushort(a) | ((unsigned)__half_as_ushort(b) << 16);
}
__device__ __forceinline__ unsigned cat_f(float a, float b) {
    return cat_h(__float2half_rn(a), __float2half_rn(b));
}
__device__ __forceinline__ float2 h2f2(unsigned u) {
    __half2 h = *(__half2*)&u;
    return __half22float2(h);
}

__device__ __forceinline__ uint32_t smem_u32(const void* p) {
    uint32_t a;
    asm("{ .reg .u64 t; cvta.to.shared.u64 t, %1; cvt.u32.u64 %0, t; }" : "=r"(a) : "l"(p));
    return a;
}

__device__ __forceinline__ void ldsm4(unsigned* r, uint32_t addr) {
    asm volatile("ldmatrix.sync.aligned.m8n8.x4.shared.b16 {%0,%1,%2,%3}, [%4];"
                 : "=r"(r[0]), "=r"(r[1]), "=r"(r[2]), "=r"(r[3]) : "r"(addr));
}

__device__ __forceinline__ void mma_f16(float* d, const unsigned* a, unsigned b0,
                                        unsigned b1) {
    asm volatile(
        "mma.sync.aligned.m16n8k16.row.col.f32.f16.f16.f32 "
        "{%0,%1,%2,%3}, {%4,%5,%6,%7}, {%8,%9}, {%0,%1,%2,%3};"
        : "+f"(d[0]), "+f"(d[1]), "+f"(d[2]), "+f"(d[3])
        : "r"(a[0]), "r"(a[1]), "r"(a[2]), "r"(a[3]), "r"(b0), "r"(b1));
}

__device__ __forceinline__ void red_v4(float* p, float a, float b, float c, float d) {
    asm volatile("red.global.add.v4.f32 [%0], {%1,%2,%3,%4};"
                 :: "l"(p), "f"(a), "f"(b), "f"(c), "f"(d) : "memory");
}

// ---------------- fp16 mega GEMM (fp16 output) ----------------------------------
// Block 128x128, warp tile 64x32 (2x4 warps), BK=64, 3 stages, 2 CTAs/SM.
#define GRS 144
#define G_ATILE 18432
#define GSTG 36864
#define NSTAGE 3
#define NCHUNK 12

__global__ __launch_bounds__(256, 2)
void gemm_mega(const __half* __restrict__ Ah, const __half* __restrict__ Bh,
               __half* __restrict__ o0, __half* __restrict__ o1,
               __half* __restrict__ o2, __half* __restrict__ o3, int M) {
    extern __shared__ char smem[];
    const uint32_t sbase = smem_u32(smem);
    const int tid = threadIdx.x;
    const int lane = tid & 31;
    const int wid = tid >> 5;
    const int wm = wid >> 2;
    const int wn = wid & 3;
    const int m0 = blockIdx.y * 128;
    const int n0 = blockIdx.x * 128;

    auto load_stage = [&](int stg, int k0) {
        uint32_t sb = sbase + stg * GSTG;
#pragma unroll
        for (int t = 0; t < 8; t++) {
            int idx = tid + t * 256;
            int r = (idx >> 3) & 127;
            int c = idx & 7;
            uint32_t dst;
            const __half* g;
            int sz = 16;
            if (idx < 1024) {
                dst = sb + r * GRS + c * 16;
                int row = m0 + r;
                if (row >= M) { row = 0; sz = 0; }
                g = Ah + (size_t)row * FF + k0 + c * 8;
            } else {
                dst = sb + G_ATILE + r * GRS + c * 16;
                g = Bh + (size_t)(n0 + r) * FF + k0 + c * 8;
            }
            asm volatile("cp.async.cg.shared.global [%0], [%1], 16, %2;"
                         :: "r"(dst), "l"(g), "r"(sz));
        }
        asm volatile("cp.async.commit_group;" ::: "memory");
    };

    float acc[4][4][4];
#pragma unroll
    for (int i = 0; i < 4; i++)
#pragma unroll
        for (int t = 0; t < 4; t++)
#pragma unroll
            for (int q = 0; q < 4; q++) acc[i][t][q] = 0.f;

    const int fr = lane & 15;
    const int fko = (lane >> 4) * 16;

    load_stage(0, 0);
    load_stage(1, 64);

#pragma unroll 1
    for (int ch = 0; ch < NCHUNK; ch++) {
        if (ch < NCHUNK - 1)
            asm volatile("cp.async.wait_group 1;" ::: "memory");
        else
            asm volatile("cp.async.wait_group 0;" ::: "memory");
        __syncthreads();
        if (ch + 2 < NCHUNK) load_stage((ch + 2) % NSTAGE, (ch + 2) * 64);

        const uint32_t sb = sbase + (ch % NSTAGE) * GSTG;
#pragma unroll
        for (int ks = 0; ks < 4; ks++) {
            unsigned ah[4][4], bh[2][4];
            const uint32_t ko = (uint32_t)(ks * 32 + fko);
#pragma unroll
            for (int i = 0; i < 4; i++) {
                uint32_t ra = sb + (uint32_t)((wm * 64 + i * 16 + fr) * GRS) + ko;
                ldsm4(ah[i], ra);
            }
#pragma unroll
            for (int j = 0; j < 2; j++) {
                uint32_t rb = sb + G_ATILE + (uint32_t)((wn * 32 + j * 16 + fr) * GRS) + ko;
                ldsm4(bh[j], rb);
            }
#pragma unroll
            for (int i = 0; i < 4; i++) {
#pragma unroll
                for (int j = 0; j < 2; j++) {
#pragma unroll
                    for (int s = 0; s < 2; s++) {
                        mma_f16(acc[i][j * 2 + s], ah[i], bh[j][s], bh[j][s + 2]);
                    }
                }
            }
        }
        __syncthreads();
    }

    const int str = blockIdx.x / 6;
    __half* Cb = (str == 0) ? o0 : (str == 1) ? o1 : (str == 2) ? o2 : o3;
    const int nbase = (blockIdx.x % 6) * 128 + wn * 32;
#pragma unroll
    for (int i = 0; i < 4; i++) {
        const int r0 = m0 + wm * 64 + i * 16 + (lane >> 2);
#pragma unroll
        for (int t = 0; t < 4; t++) {
            const int col = nbase + t * 8 + (lane & 3) * 2;
            if (r0 < M)
                *(unsigned*)(Cb + (size_t)r0 * FF + col) =
                    cat_f(acc[i][t][0], acc[i][t][1]);
            if (r0 + 8 < M)
                *(unsigned*)(Cb + (size_t)(r0 + 8) * FF + col) =
                    cat_f(acc[i][t][2], acc[i][t][3]);
        }
    }
}

// ---------------- split-K small GEMM: C[M,N] += A[M,K] * B[K,N] -----------------
#define SGK 128
__global__ __launch_bounds__(256) void smallgemm(const float* __restrict__ A,
                                                 const float* __restrict__ B,
                                                 float* __restrict__ C,
                                                 int M, int N, int K) {
    __shared__ float As[32][68];
    __shared__ float Bs[32][64];
    const int tid = threadIdx.x;
    const int n0 = blockIdx.x * 64;
    const int k0 = blockIdx.y * SGK;
    const int m0 = blockIdx.z * 64;
    const int tx = tid & 15, ty = tid >> 4;
    float acc[4][4] = {};

    for (int kt = 0; kt < SGK; kt += 32) {
        __syncthreads();
#pragma unroll
        for (int i = 0; i < 2; i++) {
            int idx = tid + i * 256;
            int r = idx >> 3, c = (idx & 7) * 4;
            float4 v = (m0 + r < M)
                           ? *(const float4*)(A + (size_t)(m0 + r) * K + k0 + kt + c)
                           : make_float4(0.f, 0.f, 0.f, 0.f);
            As[c + 0][r] = v.x;
            As[c + 1][r] = v.y;
            As[c + 2][r] = v.z;
            As[c + 3][r] = v.w;
            int rb = idx >> 4, cb = (idx & 15) * 4;
            *(float4*)&Bs[rb][cb] =
                *(const float4*)(B + (size_t)(k0 + kt + rb) * N + n0 + cb);
        }
        __syncthreads();
#pragma unroll
        for (int kk = 0; kk < 32; kk++) {
            float a0 = As[kk][ty * 4 + 0], a1 = As[kk][ty * 4 + 1];
            float a2 = As[kk][ty * 4 + 2], a3 = As[kk][ty * 4 + 3];
            float4 b = *(float4*)&Bs[kk][tx * 4];
            acc[0][0] += a0 * b.x; acc[0][1] += a0 * b.y; acc[0][2] += a0 * b.z; acc[0][3] += a0 * b.w;
            acc[1][0] += a1 * b.x; acc[1][1] += a1 * b.y; acc[1][2] += a1 * b.z; acc[1][3] += a1 * b.w;
            acc[2][0] += a2 * b.x; acc[2][1] += a2 * b.y; acc[2][2] += a2 * b.z; acc[2][3] += a2 * b.w;
            acc[3][0] += a3 * b.x; acc[3][1] += a3 * b.y; acc[3][2] += a3 * b.z; acc[3][3] += a3 * b.w;
        }
    }
#pragma unroll
    for (int i = 0; i < 4; i++) {
        int r = m0 + ty * 4 + i;
        if (r < M)
            red_v4(C + (size_t)r * N + n0 + tx * 4, acc[i][0], acc[i][1], acc[i][2],
                   acc[i][3]);
    }
}

// ---------------- prep: fp32 -> fp16 convert ------------------------------------
__global__ void cvtA_kernel(const float4* __restrict__ in, uint2* __restrict__ hi,
                            int n4) {
    int i = blockIdx.x * blockDim.x + threadIdx.x;
    if (i >= n4) return;
    float4 v = in[i];
    hi[i] = make_uint2(cat_f(v.x, v.y), cat_f(v.z, v.w));
}

// ---------------- prep: transpose-cvt of 4 matrices (mega weights) -------------
__global__ void wmegaT_kernel(const float* __restrict__ Wl, const float* __restrict__ Wr,
                              const float* __restrict__ P1, const float* __restrict__ P2,
                              __half* __restrict__ Bh) {
    __shared__ float t[32][33];
    const int k0 = blockIdx.x * 32;
    const int n0g = blockIdx.y * 32;
    const int sel = n0g / FF;
    const float* W = (sel == 0) ? Wl : (sel == 1) ? Wr : (sel == 2) ? P1 : P2;
    const int n0 = n0g - sel * FF;
    const int tx = threadIdx.x, ty = threadIdx.y;
#pragma unroll
    for (int i = 0; i < 4; i++)
        t[ty + i * 8][tx] = W[(size_t)(k0 + ty + i * 8) * FF + n0 + tx];
    __syncthreads();
#pragma unroll
    for (int i = 0; i < 4; i++)
        Bh[(size_t)(n0g + ty + i * 8) * FF + k0 + tx] = __float2half_rn(t[tx][ty + i * 8]);
}

// ---------------- fused injection attention + encoder-input assembly ----------
// Reads fp16 hl/hs/t1/t2; writes fp32 gl = a0*Gql[b]+a1*t1, gr = a0*Gqr[b]+a1*t2.
__global__ void combine2_kernel(const __half* __restrict__ hl,
                                const __half* __restrict__ hs,
                                const __half* __restrict__ t1,
                                const __half* __restrict__ t2,
                                const float* __restrict__ hqg,
                                const float* __restrict__ Gql,
                                const float* __restrict__ Gqr,
                                const int* __restrict__ batch,
                                const float* __restrict__ att,
                                float* __restrict__ gl,
                                float* __restrict__ gr) {
    int warp = (blockIdx.x * blockDim.x + threadIdx.x) >> 5;
    int lane = threadIdx.x & 31;
    if (warp >= NN) return;
    const int b = batch[warp];
    const uint4* phl = (const uint4*)(hl + (size_t)warp * FF);
    const uint4* phs = (const uint4*)(hs + (size_t)warp * FF);
    const float4* phq = (const float4*)(hqg + (size_t)b * FF);
    const float4* pat = (const float4*)att;

    float sq = 0.f, ss = 0.f;
#pragma unroll
    for (int i = 0; i < 3; i++) {
        int j = lane + i * 32;
        uint4 l8 = phl[j], s8 = phs[j];
        float4 q0 = phq[j * 2], q1 = phq[j * 2 + 1];
        float4 a0 = pat[j * 2], a1 = pat[j * 2 + 1];
        float2 l0 = h2f2(l8.x), l1 = h2f2(l8.y), l2 = h2f2(l8.z), l3 = h2f2(l8.w);
        float2 s0 = h2f2(s8.x), s1 = h2f2(s8.y), s2 = h2f2(s8.z), s3 = h2f2(s8.w);
        sq += lrelu(l0.x + q0.x) * a0.x + lrelu(l0.y + q0.y) * a0.y +
              lrelu(l1.x + q0.z) * a0.z + lrelu(l1.y + q0.w) * a0.w +
              lrelu(l2.x + q1.x) * a1.x + lrelu(l2.y + q1.y) * a1.y +
              lrelu(l3.x + q1.z) * a1.z + lrelu(l3.y + q1.w) * a1.w;
        ss += lrelu(l0.x + s0.x) * a0.x + lrelu(l0.y + s0.y) * a0.y +
              lrelu(l1.x + s1.x) * a0.z + lrelu(l1.y + s1.y) * a0.w +
              lrelu(l2.x + s2.x) * a1.x + lrelu(l2.y + s2.y) * a1.y +
              lrelu(l3.x + s3.x) * a1.z + lrelu(l3.y + s3.y) * a1.w;
    }
#pragma unroll
    for (int o = 16; o > 0; o >>= 1) {
        sq += __shfl_xor_sync(0xFFFFFFFFu, sq, o);
        ss += __shfl_xor_sync(0xFFFFFFFFu, ss, o);
    }
    float m = fmaxf(sq, ss);
    float e0 = expf(sq - m), e1 = expf(ss - m);
    float inv = 1.f / (e0 + e1);
    float a0 = e0 * inv, a1 = e1 * inv;

    const uint4* pt1 = (const uint4*)(t1 + (size_t)warp * FF);
    const uint4* pt2 = (const uint4*)(t2 + (size_t)warp * FF);
    const float4* pgl = (const float4*)(Gql + (size_t)b * FF);
    const float4* pgr = (const float4*)(Gqr + (size_t)b * FF);
    float4* ogl = (float4*)(gl + (size_t)warp * FF);
    float4* ogr = (float4*)(gr + (size_t)warp * FF);
#pragma unroll
    for (int i = 0; i < 3; i++) {
        int j = lane + i * 32;
        uint4 u8 = pt1[j];
        float4 g0 = pgl[j * 2], g1 = pgl[j * 2 + 1];
        float2 u0 = h2f2(u8.x), u1 = h2f2(u8.y), u2 = h2f2(u8.z), u3 = h2f2(u8.w);
        ogl[j * 2] = make_float4(a0 * g0.x + a1 * u0.x, a0 * g0.y + a1 * u0.y,
                                 a0 * g0.z + a1 * u1.x, a0 * g0.w + a1 * u1.y);
        ogl[j * 2 + 1] = make_float4(a0 * g1.x + a1 * u2.x, a0 * g1.y + a1 * u2.y,
                                     a0 * g1.z + a1 * u3.x, a0 * g1.w + a1 * u3.y);
        uint4 v8 = pt2[j];
        float4 h0 = pgr[j * 2], h1 = pgr[j * 2 + 1];
        float2 v0 = h2f2(v8.x), v1 = h2f2(v8.y), v2 = h2f2(v8.z), v3 = h2f2(v8.w);
        ogr[j * 2] = make_float4(a0 * h0.x + a1 * v0.x, a0 * h0.y + a1 * v0.y,
                                 a0 * h0.z + a1 * v1.x, a0 * h0.w + a1 * v1.y);
        ogr[j * 2 + 1] = make_float4(a0 * h1.x + a1 * v2.x, a0 * h1.y + a1 * v2.y,
                                     a0 * h1.z + a1 * v3.x, a0 * h1.w + a1 * v3.y);
    }
}

// ---------------- edge logits (one warp per edge, fp32 gathers) ----------------
__global__ void edge_logit_kernel(const float* __restrict__ gl,
                                  const float* __restrict__ gr,
                                  const float* __restrict__ ge,
                                  const int* __restrict__ xcoo,
                                  const float* __restrict__ att,
                                  float* __restrict__ logit) {
    int warp = (blockIdx.x * blockDim.x + threadIdx.x) >> 5;
    int lane = threadIdx.x & 31;
    if (warp >= NE) return;
    int src = xcoo[warp * 3 + 0];
    int rel = xcoo[warp * 3 + 1];
    int tgt = xcoo[warp * 3 + 2];
    const float4* pt = (const float4*)(gl + (size_t)tgt * FF);
    const float4* ps = (const float4*)(gr + (size_t)src * FF);
    const float4* pe = (const float4*)(ge + (size_t)rel * FF);
    const float4* pa = (const float4*)att;
    float s = 0.f;
#pragma unroll
    for (int i = 0; i < 6; i++) {
        int j = lane + i * 32;
        float4 t = pt[j], r = ps[j], e = pe[j], a = pa[j];
        s += lrelu(t.x + r.x + e.x) * a.x + lrelu(t.y + r.y + e.y) * a.y +
             lrelu(t.z + r.z + e.z) * a.z + lrelu(t.w + r.w + e.w) * a.w;
    }
#pragma unroll
    for (int o = 16; o > 0; o >>= 1) s += __shfl_xor_sync(0xFFFFFFFFu, s, o);
    if (lane == 0) logit[warp] = s;
}

// ---------------- segment softmax over edges (tgt) ----------------------------
__global__ void edge_max_kernel(const int* __restrict__ xcoo,
                                const float* __restrict__ logit,
                                unsigned* __restrict__ nmax) {
    int e = blockIdx.x * blockDim.x + threadIdx.x;
    if (e < NE) atomicMax(&nmax[xcoo[e * 3 + 2]], f2ord(logit[e]));
}

__global__ void edge_sum_kernel(const int* __restrict__ xcoo,
                                const float* __restrict__ logit,
                                const unsigned* __restrict__ nmax,
                                float* __restrict__ nsum) {
    int e = blockIdx.x * blockDim.x + threadIdx.x;
    if (e < NE) {
        int t = xcoo[e * 3 + 2];
        atomicAdd(&nsum[t], expf(logit[e] - ord2f(nmax[t])));
    }
}

// ---------------- message scatter (one warp per edge, red.v4) -----------------
__global__ void message_kernel(const int* __restrict__ xcoo,
                               const float* __restrict__ logit,
                               const unsigned* __restrict__ nmax,
                               const float* __restrict__ nsum,
                               const float* __restrict__ gr,
                               float* __restrict__ acc) {
    int warp = (blockIdx.x * blockDim.x + threadIdx.x) >> 5;
    int lane = threadIdx.x & 31;
    if (warp >= NE) return;
    int src = xcoo[warp * 3 + 0];
    int tgt = xcoo[warp * 3 + 2];
    float alpha = expf(logit[warp] - ord2f(nmax[tgt])) / (nsum[tgt] + 1e-16f);
    const float4* ps = (const float4*)(gr + (size_t)src * FF);
    float* pd = acc + (size_t)tgt * FF;
#pragma unroll
    for (int i = 0; i < 6; i++) {
        int j = lane + i * 32;
        float4 v = ps[j];
        red_v4(pd + j * 4, alpha * v.x, alpha * v.y, alpha * v.z, alpha * v.w);
    }
}

// ---------------- elu + gate dot (one warp per node, in-place) ----------------
__global__ void node_post_kernel(float* __restrict__ emb,
                                 const float* __restrict__ gate_W,
                                 const float* __restrict__ gate_b,
                                 float* __restrict__ gate) {
    int warp = (blockIdx.x * blockDim.x + threadIdx.x) >> 5;
    int lane = threadIdx.x & 31;
    if (warp >= NN) return;
    float4* p = (float4*)(emb + (size_t)warp * FF);
    const float4* pw = (const float4*)gate_W;
    float s = 0.f;
#pragma unroll
    for (int i = 0; i < 6; i++) {
        int j = lane + i * 32;
        float4 v = p[j];
        v.x = v.x > 0.f ? v.x : expm1f(v.x);
        v.y = v.y > 0.f ? v.y : expm1f(v.y);
        v.z = v.z > 0.f ? v.z : expm1f(v.z);
        v.w = v.w > 0.f ? v.w : expm1f(v.w);
        p[j] = v;
        float4 w = pw[j];
        s += v.x * w.x + v.y * w.y + v.z * w.z + v.w * w.w;
    }
#pragma unroll
    for (int o = 16; o > 0; o >>= 1) s += __shfl_xor_sync(0xFFFFFFFFu, s, o);
    if (lane == 0) gate[warp] = s + gate_b[0];
}

// ---------------- graph softmax over nodes ------------------------------------
__global__ void graph_max_kernel(const float* __restrict__ gate,
                                 const int* __restrict__ batch,
                                 unsigned* __restrict__ gmax) {
    int n = blockIdx.x * blockDim.x + threadIdx.x;
    if (n < NN) atomicMax(&gmax[batch[n]], f2ord(gate[n]));
}

__global__ void graph_sum_kernel(float* __restrict__ gate,
                                 const int* __restrict__ batch,
                                 const unsigned* __restrict__ gmax,
                                 float* __restrict__ gsum) {
    int n = blockIdx.x * blockDim.x + threadIdx.x;
    if (n < NN) {
        float ex = expf(gate[n] - ord2f(gmax[batch[n]]));
        gate[n] = ex;
        atomicAdd(&gsum[batch[n]], ex);
    }
}

__global__ void gscale_kernel(float* __restrict__ gate,
                              const int* __restrict__ batch,
                              const float* __restrict__ gsum) {
    int n = blockIdx.x * blockDim.x + threadIdx.x;
    if (n < NN) gate[n] = gate[n] / (gsum[batch[n]] + 1e-16f);
}

// ---------------- pooled = segment_sum(g * emb, batch) (batch is sorted) ------
__global__ void pool_kernel(const float* __restrict__ emb,
                            const float* __restrict__ g,
                            const int* __restrict__ batch,
                            float* __restrict__ pool) {
    int f = blockIdx.y * 256 + threadIdx.x;
    int n0 = blockIdx.x * 1024;
    int n1 = min(n0 + 1024, NN);
    float acc = 0.f;
    int curb = batch[n0];
    for (int n = n0; n < n1; n++) {
        int b = batch[n];
        if (b != curb) {
            atomicAdd(&pool[(size_t)curb * FF + f], acc);
            acc = 0.f;
            curb = b;
        }
        acc += g[n] * emb[(size_t)n * FF + f];
    }
    atomicAdd(&pool[(size_t)curb * FF + f], acc);
}

// ---------------- init kernels --------------------------------------------------
__global__ void init_node_kernel(unsigned* nmax, float* nsum, unsigned* gmax,
                                 float* gsum, float* pool) {
    int i = blockIdx.x * blockDim.x + threadIdx.x;
    if (i < NN) {
        nmax[i] = ENC_NEG_INF;
        nsum[i] = 0.f;
    }
    if (i < NB) {
        gmax[i] = ENC_NEG_INF;
        gsum[i] = 0.f;
    }
    if (i < NB * FF) pool[i] = 0.f;
}

__global__ void zero_kernel(float4* p, int n4) {
    int i = blockIdx.x * blockDim.x + threadIdx.x;
    if (i < n4) p[i] = make_float4(0.f, 0.f, 0.f, 0.f);
}

// ---------------- launcher -------------------------------------------------------
extern "C" void kernel_launch(void* const* d_in, const int* in_sizes, int n_in,
                              void* d_out, int out_size) {
    const float* queries = (const float*)d_in[0];
    const float* entities = (const float*)d_in[1];
    const float* relations = (const float*)d_in[2];
    const int* xcoo = (const int*)d_in[3];
    const int* batch = (const int*)d_in[4];
    const float* inj_Wl = (const float*)d_in[5];
    const float* inj_Wr = (const float*)d_in[6];
    const float* inj_att = (const float*)d_in[7];
    const float* enc_Wl = (const float*)d_in[8];
    const float* enc_Wr = (const float*)d_in[9];
    const float* enc_We = (const float*)d_in[10];
    const float* enc_att = (const float*)d_in[11];
    /* d_in[12] enc_Wrel: dead code in reference */
    const float* gate_W = (const float*)d_in[13];
    const float* gate_b = (const float*)d_in[14];
    const float* vt_W = (const float*)d_in[15];
    float* out = (float*)d_out;

    float *big0, *big1, *big2, *P, *q3, *ge, *logit, *nsum, *gate, *gsum, *pool;
    __half *h0, *h1, *h2, *h3, *Ahf, *Bhf;
    unsigned *nmax, *gmax;
    cudaGetSymbolAddress((void**)&h0, g_h0);
    cudaGetSymbolAddress((void**)&h1, g_h1);
    cudaGetSymbolAddress((void**)&h2, g_h2);
    cudaGetSymbolAddress((void**)&h3, g_h3);
    cudaGetSymbolAddress((void**)&big0, g_big0);
    cudaGetSymbolAddress((void**)&big1, g_big1);
    cudaGetSymbolAddress((void**)&big2, g_big2);
    cudaGetSymbolAddress((void**)&Ahf, g_Ahf);
    cudaGetSymbolAddress((void**)&Bhf, g_Bhf);
    cudaGetSymbolAddress((void**)&P, g_P);
    cudaGetSymbolAddress((void**)&q3, g_q3);
    cudaGetSymbolAddress((void**)&ge, g_ge);
    cudaGetSymbolAddress((void**)&logit, g_logit);
    cudaGetSymbolAddress((void**)&nmax, g_nmax);
    cudaGetSymbolAddress((void**)&nsum, g_nsum);
    cudaGetSymbolAddress((void**)&gate, g_gate);
    cudaGetSymbolAddress((void**)&gmax, g_gmax);
    cudaGetSymbolAddress((void**)&gsum, g_gsum);
    cudaGetSymbolAddress((void**)&pool, g_pool);

    float* P1 = P;
    float* P2 = P + FF * FF;
    float* hq = q3;
    float* Gql = q3 + NB * FF;
    float* Gqr = q3 + 2 * NB * FF;

    cudaFuncSetAttribute(gemm_mega, cudaFuncAttributeMaxDynamicSharedMemorySize,
                         NSTAGE * GSTG);

    init_node_kernel<<<(NN + 255) / 256, 256>>>(nmax, nsum, gmax, gsum, pool);

    // ---- prep: fp16 entities ----
    cvtA_kernel<<<(NN * FF / 4 + 255) / 256, 256>>>((const float4*)entities,
                                                    (uint2*)Ahf, NN * FF / 4);

    // ---- P1 = inj_Wr @ enc_Wl, P2 = inj_Wr @ enc_Wr (fp32 split-K) ----
    zero_kernel<<<(2 * FF * FF / 4 + 255) / 256, 256>>>((float4*)P, 2 * FF * FF / 4);
    smallgemm<<<dim3(FF / 64, FF / SGK, FF / 64), 256>>>(inj_Wr, enc_Wl, P1, FF, FF, FF);
    smallgemm<<<dim3(FF / 64, FF / SGK, FF / 64), 256>>>(inj_Wr, enc_Wr, P2, FF, FF, FF);

    // ---- hq = queries@inj_Wr; Gql = hq@enc_Wl; Gqr = hq@enc_Wr ----
    zero_kernel<<<(3 * NB * FF / 4 + 255) / 256, 256>>>((float4*)q3, 3 * NB * FF / 4);
    smallgemm<<<dim3(FF / 64, FF / SGK, 1), 256>>>(queries, inj_Wr, hq, NB, FF, FF);
    smallgemm<<<dim3(FF / 64, FF / SGK, 1), 256>>>(hq, enc_Wl, Gql, NB, FF, FF);
    smallgemm<<<dim3(FF / 64, FF / SGK, 1), 256>>>(hq, enc_Wr, Gqr, NB, FF, FF);

    // ---- ge = relations @ enc_We ----
    zero_kernel<<<(NRL * FF / 4 + 255) / 256, 256>>>((float4*)ge, NRL * FF / 4);
    smallgemm<<<dim3(FF / 64, FF / SGK, (NRL + 63) / 64), 256>>>(relations, enc_We, ge,
                                                                 NRL, FF, FF);

    // ---- fused mega weights [Wl | Wr | P1 | P2] -> Bhf fp16 ----
    wmegaT_kernel<<<dim3(FF / 32, NMEGA / 32), dim3(32, 8)>>>(inj_Wl, inj_Wr, P1, P2,
                                                              Bhf);

    // ---- mega GEMM: fp16(E) @ Bhf^T -> hl, hs, t1, t2 (fp16 outputs) ----
    gemm_mega<<<dim3(NMEGA / 128, (NN + 127) / 128), 256, NSTAGE * GSTG>>>(
        Ahf, Bhf, h0, h1, h2, h3, NN);

    // ---- injection attention + assembly -> fp32 gl/gr ----
    combine2_kernel<<<(NN * 32 + 255) / 256, 256>>>(h0, h1, h2, h3, hq, Gql, Gqr,
                                                    batch, inj_att, big0, big1);

    edge_logit_kernel<<<(NE * 32 + 255) / 256, 256>>>(big0, big1, ge, xcoo, enc_att,
                                                      logit);

    zero_kernel<<<(NN * FF / 4 + 255) / 256, 256>>>((float4*)big2, NN * FF / 4);

    edge_max_kernel<<<(NE + 255) / 256, 256>>>(xcoo, logit, nmax);
    edge_sum_kernel<<<(NE + 255) / 256, 256>>>(xcoo, logit, nmax, nsum);
    message_kernel<<<(NE * 32 + 255) / 256, 256>>>(xcoo, logit, nmax, nsum, big1, big2);

    node_post_kernel<<<(NN * 32 + 255) / 256, 256>>>(big2, gate_W, gate_b, gate);

    graph_max_kernel<<<(NN + 255) / 256, 256>>>(gate, batch, gmax);
    graph_sum_kernel<<<(NN + 255) / 256, 256>>>(gate, batch, gmax, gsum);
    gscale_kernel<<<(NN + 255) / 256, 256>>>(gate, batch, gsum);

    pool_kernel<<<dim3((NN + 1023) / 1024, 3), 256>>>(big2, gate, batch, pool);

    // out = pooled @ vt_W  [64,768]x[768,2304]
    zero_kernel<<<(NB * FV / 4 + 255) / 256, 256>>>((float4*)out, NB * FV / 4);
    smallgemm<<<dim3(FV / 64, FF / SGK, 1), 256>>>(pool, vt_W, out, NB, FV, FF);
}

// round 12
// speedup vs baseline: 1.3992x; 1.3992x over previous
#include <cuda_runtime.h>
#include <cuda_fp16.h>
#include <math.h>
#include <stdint.h>

#define NN 50000
#define NE 100000
#define NRL 500
#define NB 64
#define FF 768
#define FV 2304
#define NMEGA (4 * FF)  // 3072
#define ENC_NEG_INF 0x007FFFFFu

// ---------------- scratch (static device memory; no allocations) ------------
__device__ __align__(16) __half g_h0[NN * FF];    // hl (fp16, GEMM out)
__device__ __align__(16) __half g_h1[NN * FF];    // hs (fp16, GEMM out)
__device__ __align__(16) __half g_h2[NN * FF];    // t1 (fp16, GEMM out)
__device__ __align__(16) __half g_h3[NN * FF];    // t2 (fp16, GEMM out)
__device__ __align__(16) float g_big0[NN * FF];   // gl (fp32)
__device__ __align__(16) float g_big1[NN * FF];   // gr (fp32)
__device__ __align__(16) float g_big2[NN * FF];   // msg accum / ent_emb
__device__ __align__(16) __half g_Ahf[NN * FF];   // fp16 entities
__device__ __align__(16) __half g_Bhf[NMEGA * FF];  // [3072,768] fused W^T fp16
__device__ __align__(16) float g_P[2 * FF * FF];  // P1 | P2
__device__ __align__(16) float g_q3[3 * NB * FF];  // hq | Gql | Gqr
__device__ __align__(16) float g_ge[NRL * FF];
__device__ float g_logit[NE];
__device__ unsigned g_nmax[NN];
__device__ float g_nsum[NN];
__device__ float g_gate[NN];
__device__ unsigned g_gmax[NB];
__device__ float g_gsum[NB];
__device__ __align__(16) float g_pool[NB * FF];

// ---------------- helpers ----------------------------------------------------
__device__ __forceinline__ float lrelu(float x) { return x > 0.f ? x : 0.2f * x; }

__device__ __forceinline__ unsigned f2ord(float f) {
    unsigned u = __float_as_uint(f);
    return (u & 0x80000000u) ? ~u : (u | 0x80000000u);
}
__device__ __forceinline__ float ord2f(unsigned u) {
    return (u & 0x80000000u) ? __uint_as_float(u & 0x7FFFFFFFu) : __uint_as_float(~u);
}

__device__ __forceinline__ unsigned cat_h(__half a, __half b) {
    return (unsigned)__half_as_ushort(a) | ((unsigned)__half_as_ushort(b) << 16);
}
__device__ __forceinline__ unsigned cat_f(float a, float b) {
    return cat_h(__float2half_rn(a), __float2half_rn(b));
}
__device__ __forceinline__ float2 h2f2(unsigned u) {
    __half2 h = *(__half2*)&u;
    return __half22float2(h);
}

__device__ __forceinline__ uint32_t smem_u32(const void* p) {
    uint32_t a;
    asm("{ .reg .u64 t; cvta.to.shared.u64 t, %1; cvt.u32.u64 %0, t; }" : "=r"(a) : "l"(p));
    return a;
}

__device__ __forceinline__ void ldsm4(unsigned* r, uint32_t addr) {
    asm volatile("ldmatrix.sync.aligned.m8n8.x4.shared.b16 {%0,%1,%2,%3}, [%4];"
                 : "=r"(r[0]), "=r"(r[1]), "=r"(r[2]), "=r"(r[3]) : "r"(addr));
}

__device__ __forceinline__ void mma_f16(float* d, const unsigned* a, unsigned b0,
                                        unsigned b1) {
    asm volatile(
        "mma.sync.aligned.m16n8k16.row.col.f32.f16.f16.f32 "
        "{%0,%1,%2,%3}, {%4,%5,%6,%7}, {%8,%9}, {%0,%1,%2,%3};"
        : "+f"(d[0]), "+f"(d[1]), "+f"(d[2]), "+f"(d[3])
        : "r"(a[0]), "r"(a[1]), "r"(a[2]), "r"(a[3]), "r"(b0), "r"(b1));
}

__device__ __forceinline__ void red_v4(float* p, float a, float b, float c, float d) {
    asm volatile("red.global.add.v4.f32 [%0], {%1,%2,%3,%4};"
                 :: "l"(p), "f"(a), "f"(b), "f"(c), "f"(d) : "memory");
}

// ---------------- fp16 mega GEMM (fp16 output) ----------------------------------
// Block 128x128, warp tile 64x32 (2x4 warps), BK=64, 3 stages, 2 CTAs/SM.
#define GRS 144
#define G_ATILE 18432
#define GSTG 36864
#define NSTAGE 3
#define NCHUNK 12

__global__ __launch_bounds__(256, 2)
void gemm_mega(const __half* __restrict__ Ah, const __half* __restrict__ Bh,
               __half* __restrict__ o0, __half* __restrict__ o1,
               __half* __restrict__ o2, __half* __restrict__ o3, int M) {
    extern __shared__ char smem[];
    const uint32_t sbase = smem_u32(smem);
    const int tid = threadIdx.x;
    const int lane = tid & 31;
    const int wid = tid >> 5;
    const int wm = wid >> 2;
    const int wn = wid & 3;
    const int m0 = blockIdx.y * 128;
    const int n0 = blockIdx.x * 128;

    auto load_stage = [&](int stg, int k0) {
        uint32_t sb = sbase + stg * GSTG;
#pragma unroll
        for (int t = 0; t < 8; t++) {
            int idx = tid + t * 256;
            int r = (idx >> 3) & 127;
            int c = idx & 7;
            uint32_t dst;
            const __half* g;
            int sz = 16;
            if (idx < 1024) {
                dst = sb + r * GRS + c * 16;
                int row = m0 + r;
                if (row >= M) { row = 0; sz = 0; }
                g = Ah + (size_t)row * FF + k0 + c * 8;
            } else {
                dst = sb + G_ATILE + r * GRS + c * 16;
                g = Bh + (size_t)(n0 + r) * FF + k0 + c * 8;
            }
            asm volatile("cp.async.cg.shared.global [%0], [%1], 16, %2;"
                         :: "r"(dst), "l"(g), "r"(sz));
        }
        asm volatile("cp.async.commit_group;" ::: "memory");
    };

    float acc[4][4][4];
#pragma unroll
    for (int i = 0; i < 4; i++)
#pragma unroll
        for (int t = 0; t < 4; t++)
#pragma unroll
            for (int q = 0; q < 4; q++) acc[i][t][q] = 0.f;

    const int fr = lane & 15;
    const int fko = (lane >> 4) * 16;

    load_stage(0, 0);
    load_stage(1, 64);

#pragma unroll 1
    for (int ch = 0; ch < NCHUNK; ch++) {
        if (ch < NCHUNK - 1)
            asm volatile("cp.async.wait_group 1;" ::: "memory");
        else
            asm volatile("cp.async.wait_group 0;" ::: "memory");
        __syncthreads();
        if (ch + 2 < NCHUNK) load_stage((ch + 2) % NSTAGE, (ch + 2) * 64);

        const uint32_t sb = sbase + (ch % NSTAGE) * GSTG;
#pragma unroll
        for (int ks = 0; ks < 4; ks++) {
            unsigned ah[4][4], bh[2][4];
            const uint32_t ko = (uint32_t)(ks * 32 + fko);
#pragma unroll
            for (int i = 0; i < 4; i++) {
                uint32_t ra = sb + (uint32_t)((wm * 64 + i * 16 + fr) * GRS) + ko;
                ldsm4(ah[i], ra);
            }
#pragma unroll
            for (int j = 0; j < 2; j++) {
                uint32_t rb = sb + G_ATILE + (uint32_t)((wn * 32 + j * 16 + fr) * GRS) + ko;
                ldsm4(bh[j], rb);
            }
#pragma unroll
            for (int i = 0; i < 4; i++) {
#pragma unroll
                for (int j = 0; j < 2; j++) {
#pragma unroll
                    for (int s = 0; s < 2; s++) {
                        mma_f16(acc[i][j * 2 + s], ah[i], bh[j][s], bh[j][s + 2]);
                    }
                }
            }
        }
        __syncthreads();
    }

    const int str = blockIdx.x / 6;
    __half* Cb = (str == 0) ? o0 : (str == 1) ? o1 : (str == 2) ? o2 : o3;
    const int nbase = (blockIdx.x % 6) * 128 + wn * 32;
#pragma unroll
    for (int i = 0; i < 4; i++) {
        const int r0 = m0 + wm * 64 + i * 16 + (lane >> 2);
#pragma unroll
        for (int t = 0; t < 4; t++) {
            const int col = nbase + t * 8 + (lane & 3) * 2;
            if (r0 < M)
                *(unsigned*)(Cb + (size_t)r0 * FF + col) =
                    cat_f(acc[i][t][0], acc[i][t][1]);
            if (r0 + 8 < M)
                *(unsigned*)(Cb + (size_t)(r0 + 8) * FF + col) =
                    cat_f(acc[i][t][2], acc[i][t][3]);
        }
    }
}

// ---------------- split-K small GEMM: C[M,N] += A[M,K] * B[K,N] -----------------
#define SGK 128
__global__ __launch_bounds__(256) void smallgemm(const float* __restrict__ A,
                                                 const float* __restrict__ B,
                                                 float* __restrict__ C,
                                                 int M, int N, int K) {
    __shared__ float As[32][68];
    __shared__ float Bs[32][64];
    const int tid = threadIdx.x;
    const int n0 = blockIdx.x * 64;
    const int k0 = blockIdx.y * SGK;
    const int m0 = blockIdx.z * 64;
    const int tx = tid & 15, ty = tid >> 4;
    float acc[4][4] = {};

    for (int kt = 0; kt < SGK; kt += 32) {
        __syncthreads();
#pragma unroll
        for (int i = 0; i < 2; i++) {
            int idx = tid + i * 256;
            int r = idx >> 3, c = (idx & 7) * 4;
            float4 v = (m0 + r < M)
                           ? *(const float4*)(A + (size_t)(m0 + r) * K + k0 + kt + c)
                           : make_float4(0.f, 0.f, 0.f, 0.f);
            As[c + 0][r] = v.x;
            As[c + 1][r] = v.y;
            As[c + 2][r] = v.z;
            As[c + 3][r] = v.w;
            int rb = idx >> 4, cb = (idx & 15) * 4;
            *(float4*)&Bs[rb][cb] =
                *(const float4*)(B + (size_t)(k0 + kt + rb) * N + n0 + cb);
        }
        __syncthreads();
#pragma unroll
        for (int kk = 0; kk < 32; kk++) {
            float a0 = As[kk][ty * 4 + 0], a1 = As[kk][ty * 4 + 1];
            float a2 = As[kk][ty * 4 + 2], a3 = As[kk][ty * 4 + 3];
            float4 b = *(float4*)&Bs[kk][tx * 4];
            acc[0][0] += a0 * b.x; acc[0][1] += a0 * b.y; acc[0][2] += a0 * b.z; acc[0][3] += a0 * b.w;
            acc[1][0] += a1 * b.x; acc[1][1] += a1 * b.y; acc[1][2] += a1 * b.z; acc[1][3] += a1 * b.w;
            acc[2][0] += a2 * b.x; acc[2][1] += a2 * b.y; acc[2][2] += a2 * b.z; acc[2][3] += a2 * b.w;
            acc[3][0] += a3 * b.x; acc[3][1] += a3 * b.y; acc[3][2] += a3 * b.z; acc[3][3] += a3 * b.w;
        }
    }
#pragma unroll
    for (int i = 0; i < 4; i++) {
        int r = m0 + ty * 4 + i;
        if (r < M)
            red_v4(C + (size_t)r * N + n0 + tx * 4, acc[i][0], acc[i][1], acc[i][2],
                   acc[i][3]);
    }
}

// ---------------- prep: fp32 -> fp16 convert ------------------------------------
__global__ void cvtA_kernel(const float4* __restrict__ in, uint2* __restrict__ hi,
                            int n4) {
    int i = blockIdx.x * blockDim.x + threadIdx.x;
    if (i >= n4) return;
    float4 v = in[i];
    hi[i] = make_uint2(cat_f(v.x, v.y), cat_f(v.z, v.w));
}

// ---------------- prep: transpose-cvt of 4 matrices (mega weights) -------------
__global__ void wmegaT_kernel(const float* __restrict__ Wl, const float* __restrict__ Wr,
                              const float* __restrict__ P1, const float* __restrict__ P2,
                              __half* __restrict__ Bh) {
    __shared__ float t[32][33];
    const int k0 = blockIdx.x * 32;
    const int n0g = blockIdx.y * 32;
    const int sel = n0g / FF;
    const float* W = (sel == 0) ? Wl : (sel == 1) ? Wr : (sel == 2) ? P1 : P2;
    const int n0 = n0g - sel * FF;
    const int tx = threadIdx.x, ty = threadIdx.y;
#pragma unroll
    for (int i = 0; i < 4; i++)
        t[ty + i * 8][tx] = W[(size_t)(k0 + ty + i * 8) * FF + n0 + tx];
    __syncthreads();
#pragma unroll
    for (int i = 0; i < 4; i++)
        Bh[(size_t)(n0g + ty + i * 8) * FF + k0 + tx] = __float2half_rn(t[tx][ty + i * 8]);
}

// ---------------- fused injection attention + encoder-input assembly ----------
// Reads fp16 hl/hs/t1/t2; writes fp32 gl = a0*Gql[b]+a1*t1, gr = a0*Gqr[b]+a1*t2.
__global__ void combine2_kernel(const __half* __restrict__ hl,
                                const __half* __restrict__ hs,
                                const __half* __restrict__ t1,
                                const __half* __restrict__ t2,
                                const float* __restrict__ hqg,
                                const float* __restrict__ Gql,
                                const float* __restrict__ Gqr,
                                const int* __restrict__ batch,
                                const float* __restrict__ att,
                                float* __restrict__ gl,
                                float* __restrict__ gr) {
    int warp = (blockIdx.x * blockDim.x + threadIdx.x) >> 5;
    int lane = threadIdx.x & 31;
    if (warp >= NN) return;
    const int b = batch[warp];
    const uint4* phl = (const uint4*)(hl + (size_t)warp * FF);
    const uint4* phs = (const uint4*)(hs + (size_t)warp * FF);
    const float4* phq = (const float4*)(hqg + (size_t)b * FF);
    const float4* pat = (const float4*)att;

    float sq = 0.f, ss = 0.f;
#pragma unroll
    for (int i = 0; i < 3; i++) {
        int j = lane + i * 32;
        uint4 l8 = phl[j], s8 = phs[j];
        float4 q0 = phq[j * 2], q1 = phq[j * 2 + 1];
        float4 a0 = pat[j * 2], a1 = pat[j * 2 + 1];
        float2 l0 = h2f2(l8.x), l1 = h2f2(l8.y), l2 = h2f2(l8.z), l3 = h2f2(l8.w);
        float2 s0 = h2f2(s8.x), s1 = h2f2(s8.y), s2 = h2f2(s8.z), s3 = h2f2(s8.w);
        sq += lrelu(l0.x + q0.x) * a0.x + lrelu(l0.y + q0.y) * a0.y +
              lrelu(l1.x + q0.z) * a0.z + lrelu(l1.y + q0.w) * a0.w +
              lrelu(l2.x + q1.x) * a1.x + lrelu(l2.y + q1.y) * a1.y +
              lrelu(l3.x + q1.z) * a1.z + lrelu(l3.y + q1.w) * a1.w;
        ss += lrelu(l0.x + s0.x) * a0.x + lrelu(l0.y + s0.y) * a0.y +
              lrelu(l1.x + s1.x) * a0.z + lrelu(l1.y + s1.y) * a0.w +
              lrelu(l2.x + s2.x) * a1.x + lrelu(l2.y + s2.y) * a1.y +
              lrelu(l3.x + s3.x) * a1.z + lrelu(l3.y + s3.y) * a1.w;
    }
#pragma unroll
    for (int o = 16; o > 0; o >>= 1) {
        sq += __shfl_xor_sync(0xFFFFFFFFu, sq, o);
        ss += __shfl_xor_sync(0xFFFFFFFFu, ss, o);
    }
    float m = fmaxf(sq, ss);
    float e0 = expf(sq - m), e1 = expf(ss - m);
    float inv = 1.f / (e0 + e1);
    float a0 = e0 * inv, a1 = e1 * inv;

    const uint4* pt1 = (const uint4*)(t1 + (size_t)warp * FF);
    const uint4* pt2 = (const uint4*)(t2 + (size_t)warp * FF);
    const float4* pgl = (const float4*)(Gql + (size_t)b * FF);
    const float4* pgr = (const float4*)(Gqr + (size_t)b * FF);
    float4* ogl = (float4*)(gl + (size_t)warp * FF);
    float4* ogr = (float4*)(gr + (size_t)warp * FF);
#pragma unroll
    for (int i = 0; i < 3; i++) {
        int j = lane + i * 32;
        uint4 u8 = pt1[j];
        float4 g0 = pgl[j * 2], g1 = pgl[j * 2 + 1];
        float2 u0 = h2f2(u8.x), u1 = h2f2(u8.y), u2 = h2f2(u8.z), u3 = h2f2(u8.w);
        ogl[j * 2] = make_float4(a0 * g0.x + a1 * u0.x, a0 * g0.y + a1 * u0.y,
                                 a0 * g0.z + a1 * u1.x, a0 * g0.w + a1 * u1.y);
        ogl[j * 2 + 1] = make_float4(a0 * g1.x + a1 * u2.x, a0 * g1.y + a1 * u2.y,
                                     a0 * g1.z + a1 * u3.x, a0 * g1.w + a1 * u3.y);
        uint4 v8 = pt2[j];
        float4 h0 = pgr[j * 2], h1 = pgr[j * 2 + 1];
        float2 v0 = h2f2(v8.x), v1 = h2f2(v8.y), v2 = h2f2(v8.z), v3 = h2f2(v8.w);
        ogr[j * 2] = make_float4(a0 * h0.x + a1 * v0.x, a0 * h0.y + a1 * v0.y,
                                 a0 * h0.z + a1 * v1.x, a0 * h0.w + a1 * v1.y);
        ogr[j * 2 + 1] = make_float4(a0 * h1.x + a1 * v2.x, a0 * h1.y + a1 * v2.y,
                                     a0 * h1.z + a1 * v3.x, a0 * h1.w + a1 * v3.y);
    }
}

// ---------------- edge logits (one warp per edge, fp32 gathers) ----------------
__global__ void edge_logit_kernel(const float* __restrict__ gl,
                                  const float* __restrict__ gr,
                                  const float* __restrict__ ge,
                                  const int* __restrict__ xcoo,
                                  const float* __restrict__ att,
                                  float* __restrict__ logit) {
    int warp = (blockIdx.x * blockDim.x + threadIdx.x) >> 5;
    int lane = threadIdx.x & 31;
    if (warp >= NE) return;
    int src = xcoo[warp * 3 + 0];
    int rel = xcoo[warp * 3 + 1];
    int tgt = xcoo[warp * 3 + 2];
    const float4* pt = (const float4*)(gl + (size_t)tgt * FF);
    const float4* ps = (const float4*)(gr + (size_t)src * FF);
    const float4* pe = (const float4*)(ge + (size_t)rel * FF);
    const float4* pa = (const float4*)att;
    float s = 0.f;
#pragma unroll
    for (int i = 0; i < 6; i++) {
        int j = lane + i * 32;
        float4 t = pt[j], r = ps[j], e = pe[j], a = pa[j];
        s += lrelu(t.x + r.x + e.x) * a.x + lrelu(t.y + r.y + e.y) * a.y +
             lrelu(t.z + r.z + e.z) * a.z + lrelu(t.w + r.w + e.w) * a.w;
    }
#pragma unroll
    for (int o = 16; o > 0; o >>= 1) s += __shfl_xor_sync(0xFFFFFFFFu, s, o);
    if (lane == 0) logit[warp] = s;
}

// ---------------- segment softmax over edges (tgt) ----------------------------
__global__ void edge_max_kernel(const int* __restrict__ xcoo,
                                const float* __restrict__ logit,
                                unsigned* __restrict__ nmax) {
    int e = blockIdx.x * blockDim.x + threadIdx.x;
    if (e < NE) atomicMax(&nmax[xcoo[e * 3 + 2]], f2ord(logit[e]));
}

__global__ void edge_sum_kernel(const int* __restrict__ xcoo,
                                const float* __restrict__ logit,
                                const unsigned* __restrict__ nmax,
                                float* __restrict__ nsum) {
    int e = blockIdx.x * blockDim.x + threadIdx.x;
    if (e < NE) {
        int t = xcoo[e * 3 + 2];
        atomicAdd(&nsum[t], expf(logit[e] - ord2f(nmax[t])));
    }
}

// ---------------- message scatter (one warp per edge, red.v4) -----------------
__global__ void message_kernel(const int* __restrict__ xcoo,
                               const float* __restrict__ logit,
                               const unsigned* __restrict__ nmax,
                               const float* __restrict__ nsum,
                               const float* __restrict__ gr,
                               float* __restrict__ acc) {
    int warp = (blockIdx.x * blockDim.x + threadIdx.x) >> 5;
    int lane = threadIdx.x & 31;
    if (warp >= NE) return;
    int src = xcoo[warp * 3 + 0];
    int tgt = xcoo[warp * 3 + 2];
    float alpha = expf(logit[warp] - ord2f(nmax[tgt])) / (nsum[tgt] + 1e-16f);
    const float4* ps = (const float4*)(gr + (size_t)src * FF);
    float* pd = acc + (size_t)tgt * FF;
#pragma unroll
    for (int i = 0; i < 6; i++) {
        int j = lane + i * 32;
        float4 v = ps[j];
        red_v4(pd + j * 4, alpha * v.x, alpha * v.y, alpha * v.z, alpha * v.w);
    }
}

// ---------------- elu + gate dot (one warp per node, in-place) ----------------
__global__ void node_post_kernel(float* __restrict__ emb,
                                 const float* __restrict__ gate_W,
                                 const float* __restrict__ gate_b,
                                 float* __restrict__ gate) {
    int warp = (blockIdx.x * blockDim.x + threadIdx.x) >> 5;
    int lane = threadIdx.x & 31;
    if (warp >= NN) return;
    float4* p = (float4*)(emb + (size_t)warp * FF);
    const float4* pw = (const float4*)gate_W;
    float s = 0.f;
#pragma unroll
    for (int i = 0; i < 6; i++) {
        int j = lane + i * 32;
        float4 v = p[j];
        v.x = v.x > 0.f ? v.x : expm1f(v.x);
        v.y = v.y > 0.f ? v.y : expm1f(v.y);
        v.z = v.z > 0.f ? v.z : expm1f(v.z);
        v.w = v.w > 0.f ? v.w : expm1f(v.w);
        p[j] = v;
        float4 w = pw[j];
        s += v.x * w.x + v.y * w.y + v.z * w.z + v.w * w.w;
    }
#pragma unroll
    for (int o = 16; o > 0; o >>= 1) s += __shfl_xor_sync(0xFFFFFFFFu, s, o);
    if (lane == 0) gate[warp] = s + gate_b[0];
}

// ---------------- graph softmax over nodes ------------------------------------
__global__ void graph_max_kernel(const float* __restrict__ gate,
                                 const int* __restrict__ batch,
                                 unsigned* __restrict__ gmax) {
    int n = blockIdx.x * blockDim.x + threadIdx.x;
    if (n < NN) atomicMax(&gmax[batch[n]], f2ord(gate[n]));
}

__global__ void graph_sum_kernel(float* __restrict__ gate,
                                 const int* __restrict__ batch,
                                 const unsigned* __restrict__ gmax,
                                 float* __restrict__ gsum) {
    int n = blockIdx.x * blockDim.x + threadIdx.x;
    if (n < NN) {
        float ex = expf(gate[n] - ord2f(gmax[batch[n]]));
        gate[n] = ex;
        atomicAdd(&gsum[batch[n]], ex);
    }
}

__global__ void gscale_kernel(float* __restrict__ gate,
                              const int* __restrict__ batch,
                              const float* __restrict__ gsum) {
    int n = blockIdx.x * blockDim.x + threadIdx.x;
    if (n < NN) gate[n] = gate[n] / (gsum[batch[n]] + 1e-16f);
}

// ---------------- pooled = segment_sum(g * emb, batch) (batch is sorted) ------
__global__ void pool_kernel(const float* __restrict__ emb,
                            const float* __restrict__ g,
                            const int* __restrict__ batch,
                            float* __restrict__ pool) {
    int f = blockIdx.y * 256 + threadIdx.x;
    int n0 = blockIdx.x * 1024;
    int n1 = min(n0 + 1024, NN);
    float acc = 0.f;
    int curb = batch[n0];
    for (int n = n0; n < n1; n++) {
        int b = batch[n];
        if (b != curb) {
            atomicAdd(&pool[(size_t)curb * FF + f], acc);
            acc = 0.f;
            curb = b;
        }
        acc += g[n] * emb[(size_t)n * FF + f];
    }
    atomicAdd(&pool[(size_t)curb * FF + f], acc);
}

// ---------------- init kernels --------------------------------------------------
__global__ void init_node_kernel(unsigned* nmax, float* nsum, unsigned* gmax,
                                 float* gsum, float* pool) {
    int i = blockIdx.x * blockDim.x + threadIdx.x;
    if (i < NN) {
        nmax[i] = ENC_NEG_INF;
        nsum[i] = 0.f;
    }
    if (i < NB) {
        gmax[i] = ENC_NEG_INF;
        gsum[i] = 0.f;
    }
    if (i < NB * FF) pool[i] = 0.f;
}

__global__ void zero_kernel(float4* p, int n4) {
    int i = blockIdx.x * blockDim.x + threadIdx.x;
    if (i < n4) p[i] = make_float4(0.f, 0.f, 0.f, 0.f);
}

// ---------------- launcher -------------------------------------------------------
extern "C" void kernel_launch(void* const* d_in, const int* in_sizes, int n_in,
                              void* d_out, int out_size) {
    const float* queries = (const float*)d_in[0];
    const float* entities = (const float*)d_in[1];
    const float* relations = (const float*)d_in[2];
    const int* xcoo = (const int*)d_in[3];
    const int* batch = (const int*)d_in[4];
    const float* inj_Wl = (const float*)d_in[5];
    const float* inj_Wr = (const float*)d_in[6];
    const float* inj_att = (const float*)d_in[7];
    const float* enc_Wl = (const float*)d_in[8];
    const float* enc_Wr = (const float*)d_in[9];
    const float* enc_We = (const float*)d_in[10];
    const float* enc_att = (const float*)d_in[11];
    /* d_in[12] enc_Wrel: dead code in reference */
    const float* gate_W = (const float*)d_in[13];
    const float* gate_b = (const float*)d_in[14];
    const float* vt_W = (const float*)d_in[15];
    float* out = (float*)d_out;

    float *big0, *big1, *big2, *P, *q3, *ge, *logit, *nsum, *gate, *gsum, *pool;
    __half *h0, *h1, *h2, *h3, *Ahf, *Bhf;
    unsigned *nmax, *gmax;
    cudaGetSymbolAddress((void**)&h0, g_h0);
    cudaGetSymbolAddress((void**)&h1, g_h1);
    cudaGetSymbolAddress((void**)&h2, g_h2);
    cudaGetSymbolAddress((void**)&h3, g_h3);
    cudaGetSymbolAddress((void**)&big0, g_big0);
    cudaGetSymbolAddress((void**)&big1, g_big1);
    cudaGetSymbolAddress((void**)&big2, g_big2);
    cudaGetSymbolAddress((void**)&Ahf, g_Ahf);
    cudaGetSymbolAddress((void**)&Bhf, g_Bhf);
    cudaGetSymbolAddress((void**)&P, g_P);
    cudaGetSymbolAddress((void**)&q3, g_q3);
    cudaGetSymbolAddress((void**)&ge, g_ge);
    cudaGetSymbolAddress((void**)&logit, g_logit);
    cudaGetSymbolAddress((void**)&nmax, g_nmax);
    cudaGetSymbolAddress((void**)&nsum, g_nsum);
    cudaGetSymbolAddress((void**)&gate, g_gate);
    cudaGetSymbolAddress((void**)&gmax, g_gmax);
    cudaGetSymbolAddress((void**)&gsum, g_gsum);
    cudaGetSymbolAddress((void**)&pool, g_pool);

    float* P1 = P;
    float* P2 = P + FF * FF;
    float* hq = q3;
    float* Gql = q3 + NB * FF;
    float* Gqr = q3 + 2 * NB * FF;

    cudaFuncSetAttribute(gemm_mega, cudaFuncAttributeMaxDynamicSharedMemorySize,
                         NSTAGE * GSTG);

    init_node_kernel<<<(NN + 255) / 256, 256>>>(nmax, nsum, gmax, gsum, pool);

    // ---- prep: fp16 entities ----
    cvtA_kernel<<<(NN * FF / 4 + 255) / 256, 256>>>((const float4*)entities,
                                                    (uint2*)Ahf, NN * FF / 4);

    // ---- P1 = inj_Wr @ enc_Wl, P2 = inj_Wr @ enc_Wr (fp32 split-K) ----
    zero_kernel<<<(2 * FF * FF / 4 + 255) / 256, 256>>>((float4*)P, 2 * FF * FF / 4);
    smallgemm<<<dim3(FF / 64, FF / SGK, FF / 64), 256>>>(inj_Wr, enc_Wl, P1, FF, FF, FF);
    smallgemm<<<dim3(FF / 64, FF / SGK, FF / 64), 256>>>(inj_Wr, enc_Wr, P2, FF, FF, FF);

    // ---- hq = queries@inj_Wr; Gql = hq@enc_Wl; Gqr = hq@enc_Wr ----
    zero_kernel<<<(3 * NB * FF / 4 + 255) / 256, 256>>>((float4*)q3, 3 * NB * FF / 4);
    smallgemm<<<dim3(FF / 64, FF / SGK, 1), 256>>>(queries, inj_Wr, hq, NB, FF, FF);
    smallgemm<<<dim3(FF / 64, FF / SGK, 1), 256>>>(hq, enc_Wl, Gql, NB, FF, FF);
    smallgemm<<<dim3(FF / 64, FF / SGK, 1), 256>>>(hq, enc_Wr, Gqr, NB, FF, FF);

    // ---- ge = relations @ enc_We ----
    zero_kernel<<<(NRL * FF / 4 + 255) / 256, 256>>>((float4*)ge, NRL * FF / 4);
    smallgemm<<<dim3(FF / 64, FF / SGK, (NRL + 63) / 64), 256>>>(relations, enc_We, ge,
                                                                 NRL, FF, FF);

    // ---- fused mega weights [Wl | Wr | P1 | P2] -> Bhf fp16 ----
    wmegaT_kernel<<<dim3(FF / 32, NMEGA / 32), dim3(32, 8)>>>(inj_Wl, inj_Wr, P1, P2,
                                                              Bhf);

    // ---- mega GEMM: fp16(E) @ Bhf^T -> hl, hs, t1, t2 (fp16 outputs) ----
    gemm_mega<<<dim3(NMEGA / 128, (NN + 127) / 128), 256, NSTAGE * GSTG>>>(
        Ahf, Bhf, h0, h1, h2, h3, NN);

    // ---- injection attention + assembly -> fp32 gl/gr ----
    combine2_kernel<<<(NN * 32 + 255) / 256, 256>>>(h0, h1, h2, h3, hq, Gql, Gqr,
                                                    batch, inj_att, big0, big1);

    edge_logit_kernel<<<(NE * 32 + 255) / 256, 256>>>(big0, big1, ge, xcoo, enc_att,
                                                      logit);

    zero_kernel<<<(NN * FF / 4 + 255) / 256, 256>>>((float4*)big2, NN * FF / 4);

    edge_max_kernel<<<(NE + 255) / 256, 256>>>(xcoo, logit, nmax);
    edge_sum_kernel<<<(NE + 255) / 256, 256>>>(xcoo, logit, nmax, nsum);
    message_kernel<<<(NE * 32 + 255) / 256, 256>>>(xcoo, logit, nmax, nsum, big1, big2);

    node_post_kernel<<<(NN * 32 + 255) / 256, 256>>>(big2, gate_W, gate_b, gate);

    graph_max_kernel<<<(NN + 255) / 256, 256>>>(gate, batch, gmax);
    graph_sum_kernel<<<(NN + 255) / 256, 256>>>(gate, batch, gmax, gsum);
    gscale_kernel<<<(NN + 255) / 256, 256>>>(gate, batch, gsum);

    pool_kernel<<<dim3((NN + 1023) / 1024, 3), 256>>>(big2, gate, batch, pool);

    // out = pooled @ vt_W  [64,768]x[768,2304]
    zero_kernel<<<(NB * FV / 4 + 255) / 256, 256>>>((float4*)out, NB * FV / 4);
    smallgemm<<<dim3(FV / 64, FF / SGK, 1), 256>>>(pool, vt_W, out, NB, FV, FF);
}

// round 13
// speedup vs baseline: 1.4102x; 1.0079x over previous
#include <cuda_runtime.h>
#include <cuda_fp16.h>
#include <math.h>
#include <stdint.h>

#define NN 50000
#define NE 100000
#define NRL 500
#define NB 64
#define FF 768
#define FV 2304
#define NMEGA (4 * FF)  // 3072
#define ENC_NEG_INF 0x007FFFFFu

// ---------------- scratch (static device memory; no allocations) ------------
__device__ __align__(16) __half g_h0[NN * FF];    // hl (fp16, GEMM out)
__device__ __align__(16) __half g_h1[NN * FF];    // hs (fp16, GEMM out)
__device__ __align__(16) __half g_h2[NN * FF];    // t1 (fp16, GEMM out)
__device__ __align__(16) __half g_h3[NN * FF];    // t2 (fp16, GEMM out)
__device__ __align__(16) float g_big0[NN * FF];   // gl (fp32)
__device__ __align__(16) float g_big1[NN * FF];   // gr (fp32)
__device__ __align__(16) float g_big2[NN * FF];   // msg accum / ent_emb
__device__ __align__(16) __half g_Ahf[NN * FF];   // fp16 entities
__device__ __align__(16) __half g_Bhf[NMEGA * FF];  // [3072,768] fused W^T fp16
__device__ __align__(16) float g_P[2 * FF * FF];  // P1 | P2
__device__ __align__(16) float g_q3[3 * NB * FF];  // hq | Gql | Gqr
__device__ __align__(16) float g_ge[NRL * FF];
__device__ float g_logit[NE];
__device__ unsigned g_nmax[NN];
__device__ float g_nsum[NN];
__device__ float g_gate[NN];
__device__ unsigned g_gmax[NB];
__device__ float g_gsum[NB];
__device__ __align__(16) float g_pool[NB * FF];

// ---------------- helpers ----------------------------------------------------
__device__ __forceinline__ float lrelu(float x) { return x > 0.f ? x : 0.2f * x; }

__device__ __forceinline__ unsigned f2ord(float f) {
    unsigned u = __float_as_uint(f);
    return (u & 0x80000000u) ? ~u : (u | 0x80000000u);
}
__device__ __forceinline__ float ord2f(unsigned u) {
    return (u & 0x80000000u) ? __uint_as_float(u & 0x7FFFFFFFu) : __uint_as_float(~u);
}

__device__ __forceinline__ unsigned cat_h(__half a, __half b) {
    return (unsigned)__half_as_ushort(a) | ((unsigned)__half_as_ushort(b) << 16);
}
__device__ __forceinline__ unsigned cat_f(float a, float b) {
    return cat_h(__float2half_rn(a), __float2half_rn(b));
}
__device__ __forceinline__ float2 h2f2(unsigned u) {
    __half2 h = *(__half2*)&u;
    return __half22float2(h);
}

__device__ __forceinline__ uint32_t smem_u32(const void* p) {
    uint32_t a;
    asm("{ .reg .u64 t; cvta.to.shared.u64 t, %1; cvt.u32.u64 %0, t; }" : "=r"(a) : "l"(p));
    return a;
}

__device__ __forceinline__ void ldsm4(unsigned* r, uint32_t addr) {
    asm volatile("ldmatrix.sync.aligned.m8n8.x4.shared.b16 {%0,%1,%2,%3}, [%4];"
                 : "=r"(r[0]), "=r"(r[1]), "=r"(r[2]), "=r"(r[3]) : "r"(addr));
}

__device__ __forceinline__ void mma_f16(float* d, const unsigned* a, unsigned b0,
                                        unsigned b1) {
    asm volatile(
        "mma.sync.aligned.m16n8k16.row.col.f32.f16.f16.f32 "
        "{%0,%1,%2,%3}, {%4,%5,%6,%7}, {%8,%9}, {%0,%1,%2,%3};"
        : "+f"(d[0]), "+f"(d[1]), "+f"(d[2]), "+f"(d[3])
        : "r"(a[0]), "r"(a[1]), "r"(a[2]), "r"(a[3]), "r"(b0), "r"(b1));
}

__device__ __forceinline__ void red_v4(float* p, float a, float b, float c, float d) {
    asm volatile("red.global.add.v4.f32 [%0], {%1,%2,%3,%4};"
                 :: "l"(p), "f"(a), "f"(b), "f"(c), "f"(d) : "memory");
}

// ---------------- fp16 mega GEMM (fp16 output) ----------------------------------
// Block 128x128, warp tile 64x64 (2x2 warps, 128 threads), BK=64, 3 stages,
// 2 CTAs/SM.
#define GRS 144
#define G_ATILE 18432
#define GSTG 36864
#define NSTAGE 3
#define NCHUNK 12

__global__ __launch_bounds__(128, 2)
void gemm_mega(const __half* __restrict__ Ah, const __half* __restrict__ Bh,
               __half* __restrict__ o0, __half* __restrict__ o1,
               __half* __restrict__ o2, __half* __restrict__ o3, int M) {
    extern __shared__ char smem[];
    const uint32_t sbase = smem_u32(smem);
    const int tid = threadIdx.x;
    const int lane = tid & 31;
    const int wid = tid >> 5;
    const int wm = wid >> 1;   // 0..1
    const int wn = wid & 1;    // 0..1
    const int m0 = blockIdx.y * 128;
    const int n0 = blockIdx.x * 128;

    auto load_stage = [&](int stg, int k0) {
        uint32_t sb = sbase + stg * GSTG;
#pragma unroll
        for (int t = 0; t < 16; t++) {
            int idx = tid + t * 128;
            int r = (idx >> 3) & 127;
            int c = idx & 7;
            uint32_t dst;
            const __half* g;
            int sz = 16;
            if (idx < 1024) {
                dst = sb + r * GRS + c * 16;
                int row = m0 + r;
                if (row >= M) { row = 0; sz = 0; }
                g = Ah + (size_t)row * FF + k0 + c * 8;
            } else {
                dst = sb + G_ATILE + r * GRS + c * 16;
                g = Bh + (size_t)(n0 + r) * FF + k0 + c * 8;
            }
            asm volatile("cp.async.cg.shared.global [%0], [%1], 16, %2;"
                         :: "r"(dst), "l"(g), "r"(sz));
        }
        asm volatile("cp.async.commit_group;" ::: "memory");
    };

    float acc[4][8][4];
#pragma unroll
    for (int i = 0; i < 4; i++)
#pragma unroll
        for (int t = 0; t < 8; t++)
#pragma unroll
            for (int q = 0; q < 4; q++) acc[i][t][q] = 0.f;

    const int fr = lane & 15;
    const int fko = (lane >> 4) * 16;

    load_stage(0, 0);
    load_stage(1, 64);

#pragma unroll 1
    for (int ch = 0; ch < NCHUNK; ch++) {
        if (ch < NCHUNK - 1)
            asm volatile("cp.async.wait_group 1;" ::: "memory");
        else
            asm volatile("cp.async.wait_group 0;" ::: "memory");
        __syncthreads();
        if (ch + 2 < NCHUNK) load_stage((ch + 2) % NSTAGE, (ch + 2) * 64);

        const uint32_t sb = sbase + (ch % NSTAGE) * GSTG;
#pragma unroll
        for (int ks = 0; ks < 4; ks++) {
            unsigned ah[4][4], bh[4][4];
            const uint32_t ko = (uint32_t)(ks * 32 + fko);
#pragma unroll
            for (int i = 0; i < 4; i++) {
                uint32_t ra = sb + (uint32_t)((wm * 64 + i * 16 + fr) * GRS) + ko;
                ldsm4(ah[i], ra);
            }
#pragma unroll
            for (int j = 0; j < 4; j++) {
                uint32_t rb = sb + G_ATILE + (uint32_t)((wn * 64 + j * 16 + fr) * GRS) + ko;
                ldsm4(bh[j], rb);
            }
#pragma unroll
            for (int i = 0; i < 4; i++) {
#pragma unroll
                for (int j = 0; j < 4; j++) {
#pragma unroll
                    for (int s = 0; s < 2; s++) {
                        mma_f16(acc[i][j * 2 + s], ah[i], bh[j][s], bh[j][s + 2]);
                    }
                }
            }
        }
        __syncthreads();
    }

    const int str = blockIdx.x / 6;
    __half* Cb = (str == 0) ? o0 : (str == 1) ? o1 : (str == 2) ? o2 : o3;
    const int nbase = (blockIdx.x % 6) * 128 + wn * 64;
#pragma unroll
    for (int i = 0; i < 4; i++) {
        const int r0 = m0 + wm * 64 + i * 16 + (lane >> 2);
#pragma unroll
        for (int t = 0; t < 8; t++) {
            const int col = nbase + t * 8 + (lane & 3) * 2;
            if (r0 < M)
                *(unsigned*)(Cb + (size_t)r0 * FF + col) =
                    cat_f(acc[i][t][0], acc[i][t][1]);
            if (r0 + 8 < M)
                *(unsigned*)(Cb + (size_t)(r0 + 8) * FF + col) =
                    cat_f(acc[i][t][2], acc[i][t][3]);
        }
    }
}

// ---------------- split-K small GEMM (dual output): shared A, two B/C ----------
// grid.x in [0, 2N/64): first N/64 blocks -> B0/C0, rest -> B1/C1.
#define SGK 128
__global__ __launch_bounds__(256) void smallgemm2(const float* __restrict__ A,
                                                  const float* __restrict__ B0,
                                                  const float* __restrict__ B1,
                                                  float* __restrict__ C0,
                                                  float* __restrict__ C1,
                                                  int M, int N, int K) {
    __shared__ float As[32][68];
    __shared__ float Bs[32][64];
    const int tid = threadIdx.x;
    const int nblk = N / 64;
    const int sel = blockIdx.x / nblk;
    const float* B = sel ? B1 : B0;
    float* C = sel ? C1 : C0;
    const int n0 = (blockIdx.x - sel * nblk) * 64;
    const int k0 = blockIdx.y * SGK;
    const int m0 = blockIdx.z * 64;
    const int tx = tid & 15, ty = tid >> 4;
    float acc[4][4] = {};

    for (int kt = 0; kt < SGK; kt += 32) {
        __syncthreads();
#pragma unroll
        for (int i = 0; i < 2; i++) {
            int idx = tid + i * 256;
            int r = idx >> 3, c = (idx & 7) * 4;
            float4 v = (m0 + r < M)
                           ? *(const float4*)(A + (size_t)(m0 + r) * K + k0 + kt + c)
                           : make_float4(0.f, 0.f, 0.f, 0.f);
            As[c + 0][r] = v.x;
            As[c + 1][r] = v.y;
            As[c + 2][r] = v.z;
            As[c + 3][r] = v.w;
            int rb = idx >> 4, cb = (idx & 15) * 4;
            *(float4*)&Bs[rb][cb] =
                *(const float4*)(B + (size_t)(k0 + kt + rb) * N + n0 + cb);
        }
        __syncthreads();
#pragma unroll
        for (int kk = 0; kk < 32; kk++) {
            float a0 = As[kk][ty * 4 + 0], a1 = As[kk][ty * 4 + 1];
            float a2 = As[kk][ty * 4 + 2], a3 = As[kk][ty * 4 + 3];
            float4 b = *(float4*)&Bs[kk][tx * 4];
            acc[0][0] += a0 * b.x; acc[0][1] += a0 * b.y; acc[0][2] += a0 * b.z; acc[0][3] += a0 * b.w;
            acc[1][0] += a1 * b.x; acc[1][1] += a1 * b.y; acc[1][2] += a1 * b.z; acc[1][3] += a1 * b.w;
            acc[2][0] += a2 * b.x; acc[2][1] += a2 * b.y; acc[2][2] += a2 * b.z; acc[2][3] += a2 * b.w;
            acc[3][0] += a3 * b.x; acc[3][1] += a3 * b.y; acc[3][2] += a3 * b.z; acc[3][3] += a3 * b.w;
        }
    }
#pragma unroll
    for (int i = 0; i < 4; i++) {
        int r = m0 + ty * 4 + i;
        if (r < M)
            red_v4(C + (size_t)r * N + n0 + tx * 4, acc[i][0], acc[i][1], acc[i][2],
                   acc[i][3]);
    }
}

// ---------------- split-K small GEMM (single) ------------------------------------
__global__ __launch_bounds__(256) void smallgemm(const float* __restrict__ A,
                                                 const float* __restrict__ B,
                                                 float* __restrict__ C,
                                                 int M, int N, int K) {
    __shared__ float As[32][68];
    __shared__ float Bs[32][64];
    const int tid = threadIdx.x;
    const int n0 = blockIdx.x * 64;
    const int k0 = blockIdx.y * SGK;
    const int m0 = blockIdx.z * 64;
    const int tx = tid & 15, ty = tid >> 4;
    float acc[4][4] = {};

    for (int kt = 0; kt < SGK; kt += 32) {
        __syncthreads();
#pragma unroll
        for (int i = 0; i < 2; i++) {
            int idx = tid + i * 256;
            int r = idx >> 3, c = (idx & 7) * 4;
            float4 v = (m0 + r < M)
                           ? *(const float4*)(A + (size_t)(m0 + r) * K + k0 + kt + c)
                           : make_float4(0.f, 0.f, 0.f, 0.f);
            As[c + 0][r] = v.x;
            As[c + 1][r] = v.y;
            As[c + 2][r] = v.z;
            As[c + 3][r] = v.w;
            int rb = idx >> 4, cb = (idx & 15) * 4;
            *(float4*)&Bs[rb][cb] =
                *(const float4*)(B + (size_t)(k0 + kt + rb) * N + n0 + cb);
        }
        __syncthreads();
#pragma unroll
        for (int kk = 0; kk < 32; kk++) {
            float a0 = As[kk][ty * 4 + 0], a1 = As[kk][ty * 4 + 1];
            float a2 = As[kk][ty * 4 + 2], a3 = As[kk][ty * 4 + 3];
            float4 b = *(float4*)&Bs[kk][tx * 4];
            acc[0][0] += a0 * b.x; acc[0][1] += a0 * b.y; acc[0][2] += a0 * b.z; acc[0][3] += a0 * b.w;
            acc[1][0] += a1 * b.x; acc[1][1] += a1 * b.y; acc[1][2] += a1 * b.z; acc[1][3] += a1 * b.w;
            acc[2][0] += a2 * b.x; acc[2][1] += a2 * b.y; acc[2][2] += a2 * b.z; acc[2][3] += a2 * b.w;
            acc[3][0] += a3 * b.x; acc[3][1] += a3 * b.y; acc[3][2] += a3 * b.z; acc[3][3] += a3 * b.w;
        }
    }
#pragma unroll
    for (int i = 0; i < 4; i++) {
        int r = m0 + ty * 4 + i;
        if (r < M)
            red_v4(C + (size_t)r * N + n0 + tx * 4, acc[i][0], acc[i][1], acc[i][2],
                   acc[i][3]);
    }
}

// ---------------- prep: fp32 -> fp16 convert ------------------------------------
__global__ void cvtA_kernel(const float4* __restrict__ in, uint2* __restrict__ hi,
                            int n4) {
    int i = blockIdx.x * blockDim.x + threadIdx.x;
    if (i >= n4) return;
    float4 v = in[i];
    hi[i] = make_uint2(cat_f(v.x, v.y), cat_f(v.z, v.w));
}

// ---------------- prep: transpose-cvt of 4 matrices (mega weights) -------------
__global__ void wmegaT_kernel(const float* __restrict__ Wl, const float* __restrict__ Wr,
                              const float* __restrict__ P1, const float* __restrict__ P2,
                              __half* __restrict__ Bh) {
    __shared__ float t[32][33];
    const int k0 = blockIdx.x * 32;
    const int n0g = blockIdx.y * 32;
    const int sel = n0g / FF;
    const float* W = (sel == 0) ? Wl : (sel == 1) ? Wr : (sel == 2) ? P1 : P2;
    const int n0 = n0g - sel * FF;
    const int tx = threadIdx.x, ty = threadIdx.y;
#pragma unroll
    for (int i = 0; i < 4; i++)
        t[ty + i * 8][tx] = W[(size_t)(k0 + ty + i * 8) * FF + n0 + tx];
    __syncthreads();
#pragma unroll
    for (int i = 0; i < 4; i++)
        Bh[(size_t)(n0g + ty + i * 8) * FF + k0 + tx] = __float2half_rn(t[tx][ty + i * 8]);
}

// ---------------- fused injection attention + encoder-input assembly ----------
// Reads fp16 hl/hs/t1/t2; writes fp32 gl = a0*Gql[b]+a1*t1, gr = a0*Gqr[b]+a1*t2.
__global__ void combine2_kernel(const __half* __restrict__ hl,
                                const __half* __restrict__ hs,
                                const __half* __restrict__ t1,
                                const __half* __restrict__ t2,
                                const float* __restrict__ hqg,
                                const float* __restrict__ Gql,
                                const float* __restrict__ Gqr,
                                const int* __restrict__ batch,
                                const float* __restrict__ att,
                                float* __restrict__ gl,
                                float* __restrict__ gr) {
    int warp = (blockIdx.x * blockDim.x + threadIdx.x) >> 5;
    int lane = threadIdx.x & 31;
    if (warp >= NN) return;
    const int b = batch[warp];
    const uint4* phl = (const uint4*)(hl + (size_t)warp * FF);
    const uint4* phs = (const uint4*)(hs + (size_t)warp * FF);
    const float4* phq = (const float4*)(hqg + (size_t)b * FF);
    const float4* pat = (const float4*)att;

    float sq = 0.f, ss = 0.f;
#pragma unroll
    for (int i = 0; i < 3; i++) {
        int j = lane + i * 32;
        uint4 l8 = phl[j], s8 = phs[j];
        float4 q0 = phq[j * 2], q1 = phq[j * 2 + 1];
        float4 a0 = pat[j * 2], a1 = pat[j * 2 + 1];
        float2 l0 = h2f2(l8.x), l1 = h2f2(l8.y), l2 = h2f2(l8.z), l3 = h2f2(l8.w);
        float2 s0 = h2f2(s8.x), s1 = h2f2(s8.y), s2 = h2f2(s8.z), s3 = h2f2(s8.w);
        sq += lrelu(l0.x + q0.x) * a0.x + lrelu(l0.y + q0.y) * a0.y +
              lrelu(l1.x + q0.z) * a0.z + lrelu(l1.y + q0.w) * a0.w +
              lrelu(l2.x + q1.x) * a1.x + lrelu(l2.y + q1.y) * a1.y +
              lrelu(l3.x + q1.z) * a1.z + lrelu(l3.y + q1.w) * a1.w;
        ss += lrelu(l0.x + s0.x) * a0.x + lrelu(l0.y + s0.y) * a0.y +
              lrelu(l1.x + s1.x) * a0.z + lrelu(l1.y + s1.y) * a0.w +
              lrelu(l2.x + s2.x) * a1.x + lrelu(l2.y + s2.y) * a1.y +
              lrelu(l3.x + s3.x) * a1.z + lrelu(l3.y + s3.y) * a1.w;
    }
#pragma unroll
    for (int o = 16; o > 0; o >>= 1) {
        sq += __shfl_xor_sync(0xFFFFFFFFu, sq, o);
        ss += __shfl_xor_sync(0xFFFFFFFFu, ss, o);
    }
    float m = fmaxf(sq, ss);
    float e0 = expf(sq - m), e1 = expf(ss - m);
    float inv = 1.f / (e0 + e1);
    float a0 = e0 * inv, a1 = e1 * inv;

    const uint4* pt1 = (const uint4*)(t1 + (size_t)warp * FF);
    const uint4* pt2 = (const uint4*)(t2 + (size_t)warp * FF);
    const float4* pgl = (const float4*)(Gql + (size_t)b * FF);
    const float4* pgr = (const float4*)(Gqr + (size_t)b * FF);
    float4* ogl = (float4*)(gl + (size_t)warp * FF);
    float4* ogr = (float4*)(gr + (size_t)warp * FF);
#pragma unroll
    for (int i = 0; i < 3; i++) {
        int j = lane + i * 32;
        uint4 u8 = pt1[j];
        float4 g0 = pgl[j * 2], g1 = pgl[j * 2 + 1];
        float2 u0 = h2f2(u8.x), u1 = h2f2(u8.y), u2 = h2f2(u8.z), u3 = h2f2(u8.w);
        ogl[j * 2] = make_float4(a0 * g0.x + a1 * u0.x, a0 * g0.y + a1 * u0.y,
                                 a0 * g0.z + a1 * u1.x, a0 * g0.w + a1 * u1.y);
        ogl[j * 2 + 1] = make_float4(a0 * g1.x + a1 * u2.x, a0 * g1.y + a1 * u2.y,
                                     a0 * g1.z + a1 * u3.x, a0 * g1.w + a1 * u3.y);
        uint4 v8 = pt2[j];
        float4 h0 = pgr[j * 2], h1 = pgr[j * 2 + 1];
        float2 v0 = h2f2(v8.x), v1 = h2f2(v8.y), v2 = h2f2(v8.z), v3 = h2f2(v8.w);
        ogr[j * 2] = make_float4(a0 * h0.x + a1 * v0.x, a0 * h0.y + a1 * v0.y,
                                 a0 * h0.z + a1 * v1.x, a0 * h0.w + a1 * v1.y);
        ogr[j * 2 + 1] = make_float4(a0 * h1.x + a1 * v2.x, a0 * h1.y + a1 * v2.y,
                                     a0 * h1.z + a1 * v3.x, a0 * h1.w + a1 * v3.y);
    }
}

// ---------------- edge logits (one warp per edge, fp32 gathers) ----------------
__global__ void edge_logit_kernel(const float* __restrict__ gl,
                                  const float* __restrict__ gr,
                                  const float* __restrict__ ge,
                                  const int* __restrict__ xcoo,
                                  const float* __restrict__ att,
                                  float* __restrict__ logit) {
    int warp = (blockIdx.x * blockDim.x + threadIdx.x) >> 5;
    int lane = threadIdx.x & 31;
    if (warp >= NE) return;
    int src = xcoo[warp * 3 + 0];
    int rel = xcoo[warp * 3 + 1];
    int tgt = xcoo[warp * 3 + 2];
    const float4* pt = (const float4*)(gl + (size_t)tgt * FF);
    const float4* ps = (const float4*)(gr + (size_t)src * FF);
    const float4* pe = (const float4*)(ge + (size_t)rel * FF);
    const float4* pa = (const float4*)att;
    float s = 0.f;
#pragma unroll
    for (int i = 0; i < 6; i++) {
        int j = lane + i * 32;
        float4 t = pt[j], r = ps[j], e = pe[j], a = pa[j];
        s += lrelu(t.x + r.x + e.x) * a.x + lrelu(t.y + r.y + e.y) * a.y +
             lrelu(t.z + r.z + e.z) * a.z + lrelu(t.w + r.w + e.w) * a.w;
    }
#pragma unroll
    for (int o = 16; o > 0; o >>= 1) s += __shfl_xor_sync(0xFFFFFFFFu, s, o);
    if (lane == 0) logit[warp] = s;
}

// ---------------- segment softmax over edges (tgt) ----------------------------
__global__ void edge_max_kernel(const int* __restrict__ xcoo,
                                const float* __restrict__ logit,
                                unsigned* __restrict__ nmax) {
    int e = blockIdx.x * blockDim.x + threadIdx.x;
    if (e < NE) atomicMax(&nmax[xcoo[e * 3 + 2]], f2ord(logit[e]));
}

__global__ void edge_sum_kernel(const int* __restrict__ xcoo,
                                const float* __restrict__ logit,
                                const unsigned* __restrict__ nmax,
                                float* __restrict__ nsum) {
    int e = blockIdx.x * blockDim.x + threadIdx.x;
    if (e < NE) {
        int t = xcoo[e * 3 + 2];
        atomicAdd(&nsum[t], expf(logit[e] - ord2f(nmax[t])));
    }
}

// ---------------- message scatter (one warp per edge, red.v4) -----------------
__global__ void message_kernel(const int* __restrict__ xcoo,
                               const float* __restrict__ logit,
                               const unsigned* __restrict__ nmax,
                               const float* __restrict__ nsum,
                               const float* __restrict__ gr,
                               float* __restrict__ acc) {
    int warp = (blockIdx.x * blockDim.x + threadIdx.x) >> 5;
    int lane = threadIdx.x & 31;
    if (warp >= NE) return;
    int src = xcoo[warp * 3 + 0];
    int tgt = xcoo[warp * 3 + 2];
    float alpha = expf(logit[warp] - ord2f(nmax[tgt])) / (nsum[tgt] + 1e-16f);
    const float4* ps = (const float4*)(gr + (size_t)src * FF);
    float* pd = acc + (size_t)tgt * FF;
#pragma unroll
    for (int i = 0; i < 6; i++) {
        int j = lane + i * 32;
        float4 v = ps[j];
        red_v4(pd + j * 4, alpha * v.x, alpha * v.y, alpha * v.z, alpha * v.w);
    }
}

// ---------------- elu + gate dot (one warp per node, in-place) ----------------
__global__ void node_post_kernel(float* __restrict__ emb,
                                 const float* __restrict__ gate_W,
                                 const float* __restrict__ gate_b,
                                 float* __restrict__ gate) {
    int warp = (blockIdx.x * blockDim.x + threadIdx.x) >> 5;
    int lane = threadIdx.x & 31;
    if (warp >= NN) return;
    float4* p = (float4*)(emb + (size_t)warp * FF);
    const float4* pw = (const float4*)gate_W;
    float s = 0.f;
#pragma unroll
    for (int i = 0; i < 6; i++) {
        int j = lane + i * 32;
        float4 v = p[j];
        v.x = v.x > 0.f ? v.x : expm1f(v.x);
        v.y = v.y > 0.f ? v.y : expm1f(v.y);
        v.z = v.z > 0.f ? v.z : expm1f(v.z);
        v.w = v.w > 0.f ? v.w : expm1f(v.w);
        p[j] = v;
        float4 w = pw[j];
        s += v.x * w.x + v.y * w.y + v.z * w.z + v.w * w.w;
    }
#pragma unroll
    for (int o = 16; o > 0; o >>= 1) s += __shfl_xor_sync(0xFFFFFFFFu, s, o);
    if (lane == 0) gate[warp] = s + gate_b[0];
}

// ---------------- graph softmax over nodes ------------------------------------
__global__ void graph_max_kernel(const float* __restrict__ gate,
                                 const int* __restrict__ batch,
                                 unsigned* __restrict__ gmax) {
    int n = blockIdx.x * blockDim.x + threadIdx.x;
    if (n < NN) atomicMax(&gmax[batch[n]], f2ord(gate[n]));
}

__global__ void graph_sum_kernel(float* __restrict__ gate,
                                 const int* __restrict__ batch,
                                 const unsigned* __restrict__ gmax,
                                 float* __restrict__ gsum) {
    int n = blockIdx.x * blockDim.x + threadIdx.x;
    if (n < NN) {
        float ex = expf(gate[n] - ord2f(gmax[batch[n]]));
        gate[n] = ex;
        atomicAdd(&gsum[batch[n]], ex);
    }
}

__global__ void gscale_kernel(float* __restrict__ gate,
                              const int* __restrict__ batch,
                              const float* __restrict__ gsum) {
    int n = blockIdx.x * blockDim.x + threadIdx.x;
    if (n < NN) gate[n] = gate[n] / (gsum[batch[n]] + 1e-16f);
}

// ---------------- pooled = segment_sum(g * emb, batch) (batch is sorted) ------
__global__ void pool_kernel(const float* __restrict__ emb,
                            const float* __restrict__ g,
                            const int* __restrict__ batch,
                            float* __restrict__ pool) {
    int f = blockIdx.y * 256 + threadIdx.x;
    int n0 = blockIdx.x * 1024;
    int n1 = min(n0 + 1024, NN);
    float acc = 0.f;
    int curb = batch[n0];
    for (int n = n0; n < n1; n++) {
        int b = batch[n];
        if (b != curb) {
            atomicAdd(&pool[(size_t)curb * FF + f], acc);
            acc = 0.f;
            curb = b;
        }
        acc += g[n] * emb[(size_t)n * FF + f];
    }
    atomicAdd(&pool[(size_t)curb * FF + f], acc);
}

// ---------------- init kernels --------------------------------------------------
__global__ void init_node_kernel(unsigned* nmax, float* nsum, unsigned* gmax,
                                 float* gsum, float* pool) {
    int i = blockIdx.x * blockDim.x + threadIdx.x;
    if (i < NN) {
        nmax[i] = ENC_NEG_INF;
        nsum[i] = 0.f;
    }
    if (i < NB) {
        gmax[i] = ENC_NEG_INF;
        gsum[i] = 0.f;
    }
    if (i < NB * FF) pool[i] = 0.f;
}

__global__ void zero_kernel(float4* p, int n4) {
    int i = blockIdx.x * blockDim.x + threadIdx.x;
    if (i < n4) p[i] = make_float4(0.f, 0.f, 0.f, 0.f);
}

// ---------------- launcher -------------------------------------------------------
extern "C" void kernel_launch(void* const* d_in, const int* in_sizes, int n_in,
                              void* d_out, int out_size) {
    const float* queries = (const float*)d_in[0];
    const float* entities = (const float*)d_in[1];
    const float* relations = (const float*)d_in[2];
    const int* xcoo = (const int*)d_in[3];
    const int* batch = (const int*)d_in[4];
    const float* inj_Wl = (const float*)d_in[5];
    const float* inj_Wr = (const float*)d_in[6];
    const float* inj_att = (const float*)d_in[7];
    const float* enc_Wl = (const float*)d_in[8];
    const float* enc_Wr = (const float*)d_in[9];
    const float* enc_We = (const float*)d_in[10];
    const float* enc_att = (const float*)d_in[11];
    /* d_in[12] enc_Wrel: dead code in reference */
    const float* gate_W = (const float*)d_in[13];
    const float* gate_b = (const float*)d_in[14];
    const float* vt_W = (const float*)d_in[15];
    float* out = (float*)d_out;

    float *big0, *big1, *big2, *P, *q3, *ge, *logit, *nsum, *gate, *gsum, *pool;
    __half *h0, *h1, *h2, *h3, *Ahf, *Bhf;
    unsigned *nmax, *gmax;
    cudaGetSymbolAddress((void**)&h0, g_h0);
    cudaGetSymbolAddress((void**)&h1, g_h1);
    cudaGetSymbolAddress((void**)&h2, g_h2);
    cudaGetSymbolAddress((void**)&h3, g_h3);
    cudaGetSymbolAddress((void**)&big0, g_big0);
    cudaGetSymbolAddress((void**)&big1, g_big1);
    cudaGetSymbolAddress((void**)&big2, g_big2);
    cudaGetSymbolAddress((void**)&Ahf, g_Ahf);
    cudaGetSymbolAddress((void**)&Bhf, g_Bhf);
    cudaGetSymbolAddress((void**)&P, g_P);
    cudaGetSymbolAddress((void**)&q3, g_q3);
    cudaGetSymbolAddress((void**)&ge, g_ge);
    cudaGetSymbolAddress((void**)&logit, g_logit);
    cudaGetSymbolAddress((void**)&nmax, g_nmax);
    cudaGetSymbolAddress((void**)&nsum, g_nsum);
    cudaGetSymbolAddress((void**)&gate, g_gate);
    cudaGetSymbolAddress((void**)&gmax, g_gmax);
    cudaGetSymbolAddress((void**)&gsum, g_gsum);
    cudaGetSymbolAddress((void**)&pool, g_pool);

    float* P1 = P;
    float* P2 = P + FF * FF;
    float* hq = q3;
    float* Gql = q3 + NB * FF;
    float* Gqr = q3 + 2 * NB * FF;

    cudaFuncSetAttribute(gemm_mega, cudaFuncAttributeMaxDynamicSharedMemorySize,
                         NSTAGE * GSTG);

    init_node_kernel<<<(NN + 255) / 256, 256>>>(nmax, nsum, gmax, gsum, pool);

    // ---- prep: fp16 entities ----
    cvtA_kernel<<<(NN * FF / 4 + 255) / 256, 256>>>((const float4*)entities,
                                                    (uint2*)Ahf, NN * FF / 4);

    // ---- P1 = inj_Wr @ enc_Wl, P2 = inj_Wr @ enc_Wr (fused split-K) ----
    zero_kernel<<<(2 * FF * FF / 4 + 255) / 256, 256>>>((float4*)P, 2 * FF * FF / 4);
    smallgemm2<<<dim3(2 * FF / 64, FF / SGK, FF / 64), 256>>>(inj_Wr, enc_Wl, enc_Wr,
                                                              P1, P2, FF, FF, FF);

    // ---- hq = queries@inj_Wr; then Gql/Gqr = hq@{enc_Wl,enc_Wr} (fused) ----
    zero_kernel<<<(3 * NB * FF / 4 + 255) / 256, 256>>>((float4*)q3, 3 * NB * FF / 4);
    smallgemm<<<dim3(FF / 64, FF / SGK, 1), 256>>>(queries, inj_Wr, hq, NB, FF, FF);
    smallgemm2<<<dim3(2 * FF / 64, FF / SGK, 1), 256>>>(hq, enc_Wl, enc_Wr, Gql, Gqr,
                                                        NB, FF, FF);

    // ---- ge = relations @ enc_We ----
    zero_kernel<<<(NRL * FF / 4 + 255) / 256, 256>>>((float4*)ge, NRL * FF / 4);
    smallgemm<<<dim3(FF / 64, FF / SGK, (NRL + 63) / 64), 256>>>(relations, enc_We, ge,
                                                                 NRL, FF, FF);

    // ---- fused mega weights [Wl | Wr | P1 | P2] -> Bhf fp16 ----
    wmegaT_kernel<<<dim3(FF / 32, NMEGA / 32), dim3(32, 8)>>>(inj_Wl, inj_Wr, P1, P2,
                                                              Bhf);

    // ---- mega GEMM: fp16(E) @ Bhf^T -> hl, hs, t1, t2 (fp16 outputs) ----
    gemm_mega<<<dim3(NMEGA / 128, (NN + 127) / 128), 128, NSTAGE * GSTG>>>(
        Ahf, Bhf, h0, h1, h2, h3, NN);

    // ---- injection attention + assembly -> fp32 gl/gr ----
    combine2_kernel<<<(NN * 32 + 255) / 256, 256>>>(h0, h1, h2, h3, hq, Gql, Gqr,
                                                    batch, inj_att, big0, big1);

    edge_logit_kernel<<<(NE * 32 + 255) / 256, 256>>>(big0, big1, ge, xcoo, enc_att,
                                                      logit);

    zero_kernel<<<(NN * FF / 4 + 255) / 256, 256>>>((float4*)big2, NN * FF / 4);

    edge_max_kernel<<<(NE + 255) / 256, 256>>>(xcoo, logit, nmax);
    edge_sum_kernel<<<(NE + 255) / 256, 256>>>(xcoo, logit, nmax, nsum);
    message_kernel<<<(NE * 32 + 255) / 256, 256>>>(xcoo, logit, nmax, nsum, big1, big2);

    node_post_kernel<<<(NN * 32 + 255) / 256, 256>>>(big2, gate_W, gate_b, gate);

    graph_max_kernel<<<(NN + 255) / 256, 256>>>(gate, batch, gmax);
    graph_sum_kernel<<<(NN + 255) / 256, 256>>>(gate, batch, gmax, gsum);
    gscale_kernel<<<(NN + 255) / 256, 256>>>(gate, batch, gsum);

    pool_kernel<<<dim3((NN + 1023) / 1024, 3), 256>>>(big2, gate, batch, pool);

    // out = pooled @ vt_W  [64,768]x[768,2304]
    zero_kernel<<<(NB * FV / 4 + 255) / 256, 256>>>((float4*)out, NB * FV / 4);
    smallgemm<<<dim3(FV / 64, FF / SGK, 1), 256>>>(pool, vt_W, out, NB, FV, FF);
}

// round 14
// speedup vs baseline: 1.4425x; 1.0229x over previous
#include <cuda_runtime.h>
#include <cuda_fp16.h>
#include <math.h>
#include <stdint.h>

#define NN 50000
#define NE 100000
#define NRL 500
#define NB 64
#define FF 768
#define FV 2304
#define NMEGA (4 * FF)  // 3072
#define ENC_NEG_INF 0x007FFFFFu

// ---------------- scratch (static device memory; no allocations) ------------
__device__ __align__(16) __half g_h0[NN * FF];    // hl (fp16, GEMM out)
__device__ __align__(16) __half g_h1[NN * FF];    // hs (fp16, GEMM out)
__device__ __align__(16) __half g_h2[NN * FF];    // t1 -> gl (fp16, in-place)
__device__ __align__(16) __half g_h3[NN * FF];    // t2 -> gr (fp16, in-place)
__device__ __align__(16) float g_big2[NN * FF];   // msg accum / ent_emb
__device__ __align__(16) __half g_Ahf[NN * FF];   // fp16 entities
__device__ __align__(16) __half g_Bhf[NMEGA * FF];  // [3072,768] fused W^T fp16
__device__ __align__(16) float g_P[2 * FF * FF];  // P1 | P2
__device__ __align__(16) float g_q3[3 * NB * FF];  // hq | Gql | Gqr
__device__ __align__(16) float g_ge[NRL * FF];
__device__ float g_logit[NE];
__device__ unsigned g_nmax[NN];
__device__ float g_nsum[NN];
__device__ float g_gate[NN];
__device__ unsigned g_gmax[NB];
__device__ float g_gsum[NB];
__device__ __align__(16) float g_pool[NB * FF];

// ---------------- helpers ----------------------------------------------------
__device__ __forceinline__ float lrelu(float x) { return x > 0.f ? x : 0.2f * x; }

__device__ __forceinline__ unsigned f2ord(float f) {
    unsigned u = __float_as_uint(f);
    return (u & 0x80000000u) ? ~u : (u | 0x80000000u);
}
__device__ __forceinline__ float ord2f(unsigned u) {
    return (u & 0x80000000u) ? __uint_as_float(u & 0x7FFFFFFFu) : __uint_as_float(~u);
}

__device__ __forceinline__ unsigned cat_h(__half a, __half b) {
    return (unsigned)__half_as_ushort(a) | ((unsigned)__half_as_ushort(b) << 16);
}
__device__ __forceinline__ unsigned cat_f(float a, float b) {
    return cat_h(__float2half_rn(a), __float2half_rn(b));
}
__device__ __forceinline__ float2 h2f2(unsigned u) {
    __half2 h = *(__half2*)&u;
    return __half22float2(h);
}

__device__ __forceinline__ uint32_t smem_u32(const void* p) {
    uint32_t a;
    asm("{ .reg .u64 t; cvta.to.shared.u64 t, %1; cvt.u32.u64 %0, t; }" : "=r"(a) : "l"(p));
    return a;
}

__device__ __forceinline__ void ldsm4(unsigned* r, uint32_t addr) {
    asm volatile("ldmatrix.sync.aligned.m8n8.x4.shared.b16 {%0,%1,%2,%3}, [%4];"
                 : "=r"(r[0]), "=r"(r[1]), "=r"(r[2]), "=r"(r[3]) : "r"(addr));
}

__device__ __forceinline__ void mma_f16(float* d, const unsigned* a, unsigned b0,
                                        unsigned b1) {
    asm volatile(
        "mma.sync.aligned.m16n8k16.row.col.f32.f16.f16.f32 "
        "{%0,%1,%2,%3}, {%4,%5,%6,%7}, {%8,%9}, {%0,%1,%2,%3};"
        : "+f"(d[0]), "+f"(d[1]), "+f"(d[2]), "+f"(d[3])
        : "r"(a[0]), "r"(a[1]), "r"(a[2]), "r"(a[3]), "r"(b0), "r"(b1));
}

__device__ __forceinline__ void red_v4(float* p, float a, float b, float c, float d) {
    asm volatile("red.global.add.v4.f32 [%0], {%1,%2,%3,%4};"
                 :: "l"(p), "f"(a), "f"(b), "f"(c), "f"(d) : "memory");
}

// ---------------- fp16 mega GEMM (fp16 output) ----------------------------------
// Block 128x128, warp tile 64x64 (2x2 warps, 128 threads), BK=64, 3 stages,
// 2 CTAs/SM.
#define GRS 144
#define G_ATILE 18432
#define GSTG 36864
#define NSTAGE 3
#define NCHUNK 12

__global__ __launch_bounds__(128, 2)
void gemm_mega(const __half* __restrict__ Ah, const __half* __restrict__ Bh,
               __half* __restrict__ o0, __half* __restrict__ o1,
               __half* __restrict__ o2, __half* __restrict__ o3, int M) {
    extern __shared__ char smem[];
    const uint32_t sbase = smem_u32(smem);
    const int tid = threadIdx.x;
    const int lane = tid & 31;
    const int wid = tid >> 5;
    const int wm = wid >> 1;
    const int wn = wid & 1;
    const int m0 = blockIdx.y * 128;
    const int n0 = blockIdx.x * 128;

    auto load_stage = [&](int stg, int k0) {
        uint32_t sb = sbase + stg * GSTG;
#pragma unroll
        for (int t = 0; t < 16; t++) {
            int idx = tid + t * 128;
            int r = (idx >> 3) & 127;
            int c = idx & 7;
            uint32_t dst;
            const __half* g;
            int sz = 16;
            if (idx < 1024) {
                dst = sb + r * GRS + c * 16;
                int row = m0 + r;
                if (row >= M) { row = 0; sz = 0; }
                g = Ah + (size_t)row * FF + k0 + c * 8;
            } else {
                dst = sb + G_ATILE + r * GRS + c * 16;
                g = Bh + (size_t)(n0 + r) * FF + k0 + c * 8;
            }
            asm volatile("cp.async.cg.shared.global [%0], [%1], 16, %2;"
                         :: "r"(dst), "l"(g), "r"(sz));
        }
        asm volatile("cp.async.commit_group;" ::: "memory");
    };

    float acc[4][8][4];
#pragma unroll
    for (int i = 0; i < 4; i++)
#pragma unroll
        for (int t = 0; t < 8; t++)
#pragma unroll
            for (int q = 0; q < 4; q++) acc[i][t][q] = 0.f;

    const int fr = lane & 15;
    const int fko = (lane >> 4) * 16;

    load_stage(0, 0);
    load_stage(1, 64);

#pragma unroll 1
    for (int ch = 0; ch < NCHUNK; ch++) {
        if (ch < NCHUNK - 1)
            asm volatile("cp.async.wait_group 1;" ::: "memory");
        else
            asm volatile("cp.async.wait_group 0;" ::: "memory");
        __syncthreads();
        if (ch + 2 < NCHUNK) load_stage((ch + 2) % NSTAGE, (ch + 2) * 64);

        const uint32_t sb = sbase + (ch % NSTAGE) * GSTG;
#pragma unroll
        for (int ks = 0; ks < 4; ks++) {
            unsigned ah[4][4], bh[4][4];
            const uint32_t ko = (uint32_t)(ks * 32 + fko);
#pragma unroll
            for (int i = 0; i < 4; i++) {
                uint32_t ra = sb + (uint32_t)((wm * 64 + i * 16 + fr) * GRS) + ko;
                ldsm4(ah[i], ra);
            }
#pragma unroll
            for (int j = 0; j < 4; j++) {
                uint32_t rb = sb + G_ATILE + (uint32_t)((wn * 64 + j * 16 + fr) * GRS) + ko;
                ldsm4(bh[j], rb);
            }
#pragma unroll
            for (int i = 0; i < 4; i++) {
#pragma unroll
                for (int j = 0; j < 4; j++) {
#pragma unroll
                    for (int s = 0; s < 2; s++) {
                        mma_f16(acc[i][j * 2 + s], ah[i], bh[j][s], bh[j][s + 2]);
                    }
                }
            }
        }
        __syncthreads();
    }

    const int str = blockIdx.x / 6;
    __half* Cb = (str == 0) ? o0 : (str == 1) ? o1 : (str == 2) ? o2 : o3;
    const int nbase = (blockIdx.x % 6) * 128 + wn * 64;
#pragma unroll
    for (int i = 0; i < 4; i++) {
        const int r0 = m0 + wm * 64 + i * 16 + (lane >> 2);
#pragma unroll
        for (int t = 0; t < 8; t++) {
            const int col = nbase + t * 8 + (lane & 3) * 2;
            if (r0 < M)
                *(unsigned*)(Cb + (size_t)r0 * FF + col) =
                    cat_f(acc[i][t][0], acc[i][t][1]);
            if (r0 + 8 < M)
                *(unsigned*)(Cb + (size_t)(r0 + 8) * FF + col) =
                    cat_f(acc[i][t][2], acc[i][t][3]);
        }
    }
}

// ---------------- split-K small GEMM (dual output): shared A, two B/C ----------
#define SGK 128
__global__ __launch_bounds__(256) void smallgemm2(const float* __restrict__ A,
                                                  const float* __restrict__ B0,
                                                  const float* __restrict__ B1,
                                                  float* __restrict__ C0,
                                                  float* __restrict__ C1,
                                                  int M, int N, int K) {
    __shared__ float As[32][68];
    __shared__ float Bs[32][64];
    const int tid = threadIdx.x;
    const int nblk = N / 64;
    const int sel = blockIdx.x / nblk;
    const float* B = sel ? B1 : B0;
    float* C = sel ? C1 : C0;
    const int n0 = (blockIdx.x - sel * nblk) * 64;
    const int k0 = blockIdx.y * SGK;
    const int m0 = blockIdx.z * 64;
    const int tx = tid & 15, ty = tid >> 4;
    float acc[4][4] = {};

    for (int kt = 0; kt < SGK; kt += 32) {
        __syncthreads();
#pragma unroll
        for (int i = 0; i < 2; i++) {
            int idx = tid + i * 256;
            int r = idx >> 3, c = (idx & 7) * 4;
            float4 v = (m0 + r < M)
                           ? *(const float4*)(A + (size_t)(m0 + r) * K + k0 + kt + c)
                           : make_float4(0.f, 0.f, 0.f, 0.f);
            As[c + 0][r] = v.x;
            As[c + 1][r] = v.y;
            As[c + 2][r] = v.z;
            As[c + 3][r] = v.w;
            int rb = idx >> 4, cb = (idx & 15) * 4;
            *(float4*)&Bs[rb][cb] =
                *(const float4*)(B + (size_t)(k0 + kt + rb) * N + n0 + cb);
        }
        __syncthreads();
#pragma unroll
        for (int kk = 0; kk < 32; kk++) {
            float a0 = As[kk][ty * 4 + 0], a1 = As[kk][ty * 4 + 1];
            float a2 = As[kk][ty * 4 + 2], a3 = As[kk][ty * 4 + 3];
            float4 b = *(float4*)&Bs[kk][tx * 4];
            acc[0][0] += a0 * b.x; acc[0][1] += a0 * b.y; acc[0][2] += a0 * b.z; acc[0][3] += a0 * b.w;
            acc[1][0] += a1 * b.x; acc[1][1] += a1 * b.y; acc[1][2] += a1 * b.z; acc[1][3] += a1 * b.w;
            acc[2][0] += a2 * b.x; acc[2][1] += a2 * b.y; acc[2][2] += a2 * b.z; acc[2][3] += a2 * b.w;
            acc[3][0] += a3 * b.x; acc[3][1] += a3 * b.y; acc[3][2] += a3 * b.z; acc[3][3] += a3 * b.w;
        }
    }
#pragma unroll
    for (int i = 0; i < 4; i++) {
        int r = m0 + ty * 4 + i;
        if (r < M)
            red_v4(C + (size_t)r * N + n0 + tx * 4, acc[i][0], acc[i][1], acc[i][2],
                   acc[i][3]);
    }
}

// ---------------- split-K small GEMM (single) ------------------------------------
__global__ __launch_bounds__(256) void smallgemm(const float* __restrict__ A,
                                                 const float* __restrict__ B,
                                                 float* __restrict__ C,
                                                 int M, int N, int K) {
    __shared__ float As[32][68];
    __shared__ float Bs[32][64];
    const int tid = threadIdx.x;
    const int n0 = blockIdx.x * 64;
    const int k0 = blockIdx.y * SGK;
    const int m0 = blockIdx.z * 64;
    const int tx = tid & 15, ty = tid >> 4;
    float acc[4][4] = {};

    for (int kt = 0; kt < SGK; kt += 32) {
        __syncthreads();
#pragma unroll
        for (int i = 0; i < 2; i++) {
            int idx = tid + i * 256;
            int r = idx >> 3, c = (idx & 7) * 4;
            float4 v = (m0 + r < M)
                           ? *(const float4*)(A + (size_t)(m0 + r) * K + k0 + kt + c)
                           : make_float4(0.f, 0.f, 0.f, 0.f);
            As[c + 0][r] = v.x;
            As[c + 1][r] = v.y;
            As[c + 2][r] = v.z;
            As[c + 3][r] = v.w;
            int rb = idx >> 4, cb = (idx & 15) * 4;
            *(float4*)&Bs[rb][cb] =
                *(const float4*)(B + (size_t)(k0 + kt + rb) * N + n0 + cb);
        }
        __syncthreads();
#pragma unroll
        for (int kk = 0; kk < 32; kk++) {
            float a0 = As[kk][ty * 4 + 0], a1 = As[kk][ty * 4 + 1];
            float a2 = As[kk][ty * 4 + 2], a3 = As[kk][ty * 4 + 3];
            float4 b = *(float4*)&Bs[kk][tx * 4];
            acc[0][0] += a0 * b.x; acc[0][1] += a0 * b.y; acc[0][2] += a0 * b.z; acc[0][3] += a0 * b.w;
            acc[1][0] += a1 * b.x; acc[1][1] += a1 * b.y; acc[1][2] += a1 * b.z; acc[1][3] += a1 * b.w;
            acc[2][0] += a2 * b.x; acc[2][1] += a2 * b.y; acc[2][2] += a2 * b.z; acc[2][3] += a2 * b.w;
            acc[3][0] += a3 * b.x; acc[3][1] += a3 * b.y; acc[3][2] += a3 * b.z; acc[3][3] += a3 * b.w;
        }
    }
#pragma unroll
    for (int i = 0; i < 4; i++) {
        int r = m0 + ty * 4 + i;
        if (r < M)
            red_v4(C + (size_t)r * N + n0 + tx * 4, acc[i][0], acc[i][1], acc[i][2],
                   acc[i][3]);
    }
}

// ---------------- prep: fp32 -> fp16 convert ------------------------------------
__global__ void cvtA_kernel(const float4* __restrict__ in, uint2* __restrict__ hi,
                            int n4) {
    int i = blockIdx.x * blockDim.x + threadIdx.x;
    if (i >= n4) return;
    float4 v = in[i];
    hi[i] = make_uint2(cat_f(v.x, v.y), cat_f(v.z, v.w));
}

// ---------------- prep: transpose-cvt of 4 matrices (mega weights) -------------
__global__ void wmegaT_kernel(const float* __restrict__ Wl, const float* __restrict__ Wr,
                              const float* __restrict__ P1, const float* __restrict__ P2,
                              __half* __restrict__ Bh) {
    __shared__ float t[32][33];
    const int k0 = blockIdx.x * 32;
    const int n0g = blockIdx.y * 32;
    const int sel = n0g / FF;
    const float* W = (sel == 0) ? Wl : (sel == 1) ? Wr : (sel == 2) ? P1 : P2;
    const int n0 = n0g - sel * FF;
    const int tx = threadIdx.x, ty = threadIdx.y;
#pragma unroll
    for (int i = 0; i < 4; i++)
        t[ty + i * 8][tx] = W[(size_t)(k0 + ty + i * 8) * FF + n0 + tx];
    __syncthreads();
#pragma unroll
    for (int i = 0; i < 4; i++)
        Bh[(size_t)(n0g + ty + i * 8) * FF + k0 + tx] = __float2half_rn(t[tx][ty + i * 8]);
}

// ---------------- fused injection attention + encoder-input assembly ----------
// Reads fp16 hl/hs/t1/t2; writes fp16 gl/gr IN-PLACE over t1/t2 (per-row,
// read-before-write within each iteration -> safe).
__global__ void combine2_kernel(const __half* __restrict__ hl,
                                const __half* __restrict__ hs,
                                __half* __restrict__ t1,     // in: t1, out: gl
                                __half* __restrict__ t2,     // in: t2, out: gr
                                const float* __restrict__ hqg,
                                const float* __restrict__ Gql,
                                const float* __restrict__ Gqr,
                                const int* __restrict__ batch,
                                const float* __restrict__ att) {
    int warp = (blockIdx.x * blockDim.x + threadIdx.x) >> 5;
    int lane = threadIdx.x & 31;
    if (warp >= NN) return;
    const int b = batch[warp];
    const uint4* phl = (const uint4*)(hl + (size_t)warp * FF);
    const uint4* phs = (const uint4*)(hs + (size_t)warp * FF);
    const float4* phq = (const float4*)(hqg + (size_t)b * FF);
    const float4* pat = (const float4*)att;

    float sq = 0.f, ss = 0.f;
#pragma unroll
    for (int i = 0; i < 3; i++) {
        int j = lane + i * 32;
        uint4 l8 = phl[j], s8 = phs[j];
        float4 q0 = phq[j * 2], q1 = phq[j * 2 + 1];
        float4 a0 = pat[j * 2], a1 = pat[j * 2 + 1];
        float2 l0 = h2f2(l8.x), l1 = h2f2(l8.y), l2 = h2f2(l8.z), l3 = h2f2(l8.w);
        float2 s0 = h2f2(s8.x), s1 = h2f2(s8.y), s2 = h2f2(s8.z), s3 = h2f2(s8.w);
        sq += lrelu(l0.x + q0.x) * a0.x + lrelu(l0.y + q0.y) * a0.y +
              lrelu(l1.x + q0.z) * a0.z + lrelu(l1.y + q0.w) * a0.w +
              lrelu(l2.x + q1.x) * a1.x + lrelu(l2.y + q1.y) * a1.y +
              lrelu(l3.x + q1.z) * a1.z + lrelu(l3.y + q1.w) * a1.w;
        ss += lrelu(l0.x + s0.x) * a0.x + lrelu(l0.y + s0.y) * a0.y +
              lrelu(l1.x + s1.x) * a0.z + lrelu(l1.y + s1.y) * a0.w +
              lrelu(l2.x + s2.x) * a1.x + lrelu(l2.y + s2.y) * a1.y +
              lrelu(l3.x + s3.x) * a1.z + lrelu(l3.y + s3.y) * a1.w;
    }
#pragma unroll
    for (int o = 16; o > 0; o >>= 1) {
        sq += __shfl_xor_sync(0xFFFFFFFFu, sq, o);
        ss += __shfl_xor_sync(0xFFFFFFFFu, ss, o);
    }
    float m = fmaxf(sq, ss);
    float e0 = expf(sq - m), e1 = expf(ss - m);
    float inv = 1.f / (e0 + e1);
    float a0 = e0 * inv, a1 = e1 * inv;

    uint4* pt1 = (uint4*)(t1 + (size_t)warp * FF);
    uint4* pt2 = (uint4*)(t2 + (size_t)warp * FF);
    const float4* pgl = (const float4*)(Gql + (size_t)b * FF);
    const float4* pgr = (const float4*)(Gqr + (size_t)b * FF);
#pragma unroll
    for (int i = 0; i < 3; i++) {
        int j = lane + i * 32;
        uint4 u8 = pt1[j];
        float4 g0 = pgl[j * 2], g1 = pgl[j * 2 + 1];
        float2 u0 = h2f2(u8.x), u1 = h2f2(u8.y), u2 = h2f2(u8.z), u3 = h2f2(u8.w);
        uint4 og;
        og.x = cat_f(a0 * g0.x + a1 * u0.x, a0 * g0.y + a1 * u0.y);
        og.y = cat_f(a0 * g0.z + a1 * u1.x, a0 * g0.w + a1 * u1.y);
        og.z = cat_f(a0 * g1.x + a1 * u2.x, a0 * g1.y + a1 * u2.y);
        og.w = cat_f(a0 * g1.z + a1 * u3.x, a0 * g1.w + a1 * u3.y);
        pt1[j] = og;
        uint4 v8 = pt2[j];
        float4 h0 = pgr[j * 2], h1 = pgr[j * 2 + 1];
        float2 v0 = h2f2(v8.x), v1 = h2f2(v8.y), v2 = h2f2(v8.z), v3 = h2f2(v8.w);
        uint4 orr;
        orr.x = cat_f(a0 * h0.x + a1 * v0.x, a0 * h0.y + a1 * v0.y);
        orr.y = cat_f(a0 * h0.z + a1 * v1.x, a0 * h0.w + a1 * v1.y);
        orr.z = cat_f(a0 * h1.x + a1 * v2.x, a0 * h1.y + a1 * v2.y);
        orr.w = cat_f(a0 * h1.z + a1 * v3.x, a0 * h1.w + a1 * v3.y);
        pt2[j] = orr;
    }
}

// ---------------- edge logits (one warp per edge, fp16 gathers) ----------------
__global__ void edge_logit_kernel(const __half* __restrict__ glh,
                                  const __half* __restrict__ grh,
                                  const float* __restrict__ ge,
                                  const int* __restrict__ xcoo,
                                  const float* __restrict__ att,
                                  float* __restrict__ logit) {
    int warp = (blockIdx.x * blockDim.x + threadIdx.x) >> 5;
    int lane = threadIdx.x & 31;
    if (warp >= NE) return;
    int src = xcoo[warp * 3 + 0];
    int rel = xcoo[warp * 3 + 1];
    int tgt = xcoo[warp * 3 + 2];
    const uint4* pt = (const uint4*)(glh + (size_t)tgt * FF);
    const uint4* pr = (const uint4*)(grh + (size_t)src * FF);
    const float4* pe = (const float4*)(ge + (size_t)rel * FF);
    const float4* pa = (const float4*)att;
    float s = 0.f;
#pragma unroll
    for (int i = 0; i < 3; i++) {
        int j = lane + i * 32;
        uint4 t8 = pt[j], r8 = pr[j];
        float4 e0 = pe[j * 2], e1 = pe[j * 2 + 1];
        float4 a0 = pa[j * 2], a1 = pa[j * 2 + 1];
        float2 t0 = h2f2(t8.x), t1 = h2f2(t8.y), t2 = h2f2(t8.z), t3 = h2f2(t8.w);
        float2 r0 = h2f2(r8.x), r1 = h2f2(r8.y), r2 = h2f2(r8.z), r3 = h2f2(r8.w);
        s += lrelu(t0.x + r0.x + e0.x) * a0.x + lrelu(t0.y + r0.y + e0.y) * a0.y +
             lrelu(t1.x + r1.x + e0.z) * a0.z + lrelu(t1.y + r1.y + e0.w) * a0.w +
             lrelu(t2.x + r2.x + e1.x) * a1.x + lrelu(t2.y + r2.y + e1.y) * a1.y +
             lrelu(t3.x + r3.x + e1.z) * a1.z + lrelu(t3.y + r3.y + e1.w) * a1.w;
    }
#pragma unroll
    for (int o = 16; o > 0; o >>= 1) s += __shfl_xor_sync(0xFFFFFFFFu, s, o);
    if (lane == 0) logit[warp] = s;
}

// ---------------- segment softmax over edges (tgt) ----------------------------
__global__ void edge_max_kernel(const int* __restrict__ xcoo,
                                const float* __restrict__ logit,
                                unsigned* __restrict__ nmax) {
    int e = blockIdx.x * blockDim.x + threadIdx.x;
    if (e < NE) atomicMax(&nmax[xcoo[e * 3 + 2]], f2ord(logit[e]));
}

__global__ void edge_sum_kernel(const int* __restrict__ xcoo,
                                const float* __restrict__ logit,
                                const unsigned* __restrict__ nmax,
                                float* __restrict__ nsum) {
    int e = blockIdx.x * blockDim.x + threadIdx.x;
    if (e < NE) {
        int t = xcoo[e * 3 + 2];
        atomicAdd(&nsum[t], expf(logit[e] - ord2f(nmax[t])));
    }
}

// ---------------- message scatter (one warp per edge, fp16 gather, red.v4) -----
__global__ void message_kernel(const int* __restrict__ xcoo,
                               const float* __restrict__ logit,
                               const unsigned* __restrict__ nmax,
                               const float* __restrict__ nsum,
                               const __half* __restrict__ grh,
                               float* __restrict__ acc) {
    int warp = (blockIdx.x * blockDim.x + threadIdx.x) >> 5;
    int lane = threadIdx.x & 31;
    if (warp >= NE) return;
    int src = xcoo[warp * 3 + 0];
    int tgt = xcoo[warp * 3 + 2];
    float alpha = expf(logit[warp] - ord2f(nmax[tgt])) / (nsum[tgt] + 1e-16f);
    const uint4* pr = (const uint4*)(grh + (size_t)src * FF);
    float* pd = acc + (size_t)tgt * FF;
#pragma unroll
    for (int i = 0; i < 3; i++) {
        int j = lane + i * 32;
        uint4 v = pr[j];
        float2 f0 = h2f2(v.x), f1 = h2f2(v.y), f2 = h2f2(v.z), f3 = h2f2(v.w);
        red_v4(pd + j * 8, alpha * f0.x, alpha * f0.y, alpha * f1.x, alpha * f1.y);
        red_v4(pd + j * 8 + 4, alpha * f2.x, alpha * f2.y, alpha * f3.x, alpha * f3.y);
    }
}

// ---------------- elu + gate dot (one warp per node, in-place) ----------------
__global__ void node_post_kernel(float* __restrict__ emb,
                                 const float* __restrict__ gate_W,
                                 const float* __restrict__ gate_b,
                                 float* __restrict__ gate) {
    int warp = (blockIdx.x * blockDim.x + threadIdx.x) >> 5;
    int lane = threadIdx.x & 31;
    if (warp >= NN) return;
    float4* p = (float4*)(emb + (size_t)warp * FF);
    const float4* pw = (const float4*)gate_W;
    float s = 0.f;
#pragma unroll
    for (int i = 0; i < 6; i++) {
        int j = lane + i * 32;
        float4 v = p[j];
        v.x = v.x > 0.f ? v.x : expm1f(v.x);
        v.y = v.y > 0.f ? v.y : expm1f(v.y);
        v.z = v.z > 0.f ? v.z : expm1f(v.z);
        v.w = v.w > 0.f ? v.w : expm1f(v.w);
        p[j] = v;
        float4 w = pw[j];
        s += v.x * w.x + v.y * w.y + v.z * w.z + v.w * w.w;
    }
#pragma unroll
    for (int o = 16; o > 0; o >>= 1) s += __shfl_xor_sync(0xFFFFFFFFu, s, o);
    if (lane == 0) gate[warp] = s + gate_b[0];
}

// ---------------- graph softmax over nodes ------------------------------------
__global__ void graph_max_kernel(const float* __restrict__ gate,
                                 const int* __restrict__ batch,
                                 unsigned* __restrict__ gmax) {
    int n = blockIdx.x * blockDim.x + threadIdx.x;
    if (n < NN) atomicMax(&gmax[batch[n]], f2ord(gate[n]));
}

__global__ void graph_sum_kernel(float* __restrict__ gate,
                                 const int* __restrict__ batch,
                                 const unsigned* __restrict__ gmax,
                                 float* __restrict__ gsum) {
    int n = blockIdx.x * blockDim.x + threadIdx.x;
    if (n < NN) {
        float ex = expf(gate[n] - ord2f(gmax[batch[n]]));
        gate[n] = ex;
        atomicAdd(&gsum[batch[n]], ex);
    }
}

__global__ void gscale_kernel(float* __restrict__ gate,
                              const int* __restrict__ batch,
                              const float* __restrict__ gsum) {
    int n = blockIdx.x * blockDim.x + threadIdx.x;
    if (n < NN) gate[n] = gate[n] / (gsum[batch[n]] + 1e-16f);
}

// ---------------- pooled = segment_sum(g * emb, batch) (batch is sorted) ------
__global__ void pool_kernel(const float* __restrict__ emb,
                            const float* __restrict__ g,
                            const int* __restrict__ batch,
                            float* __restrict__ pool) {
    int f = blockIdx.y * 256 + threadIdx.x;
    int n0 = blockIdx.x * 1024;
    int n1 = min(n0 + 1024, NN);
    float acc = 0.f;
    int curb = batch[n0];
    for (int n = n0; n < n1; n++) {
        int b = batch[n];
        if (b != curb) {
            atomicAdd(&pool[(size_t)curb * FF + f], acc);
            acc = 0.f;
            curb = b;
        }
        acc += g[n] * emb[(size_t)n * FF + f];
    }
    atomicAdd(&pool[(size_t)curb * FF + f], acc);
}

// ---------------- init kernels --------------------------------------------------
__global__ void init_node_kernel(unsigned* nmax, float* nsum, unsigned* gmax,
                                 float* gsum, float* pool) {
    int i = blockIdx.x * blockDim.x + threadIdx.x;
    if (i < NN) {
        nmax[i] = ENC_NEG_INF;
        nsum[i] = 0.f;
    }
    if (i < NB) {
        gmax[i] = ENC_NEG_INF;
        gsum[i] = 0.f;
    }
    if (i < NB * FF) pool[i] = 0.f;
}

__global__ void zero_kernel(float4* p, int n4) {
    int i = blockIdx.x * blockDim.x + threadIdx.x;
    if (i < n4) p[i] = make_float4(0.f, 0.f, 0.f, 0.f);
}

// ---------------- launcher -------------------------------------------------------
extern "C" void kernel_launch(void* const* d_in, const int* in_sizes, int n_in,
                              void* d_out, int out_size) {
    const float* queries = (const float*)d_in[0];
    const float* entities = (const float*)d_in[1];
    const float* relations = (const float*)d_in[2];
    const int* xcoo = (const int*)d_in[3];
    const int* batch = (const int*)d_in[4];
    const float* inj_Wl = (const float*)d_in[5];
    const float* inj_Wr = (const float*)d_in[6];
    const float* inj_att = (const float*)d_in[7];
    const float* enc_Wl = (const float*)d_in[8];
    const float* enc_Wr = (const float*)d_in[9];
    const float* enc_We = (const float*)d_in[10];
    const float* enc_att = (const float*)d_in[11];
    /* d_in[12] enc_Wrel: dead code in reference */
    const float* gate_W = (const float*)d_in[13];
    const float* gate_b = (const float*)d_in[14];
    const float* vt_W = (const float*)d_in[15];
    float* out = (float*)d_out;

    float *big2, *P, *q3, *ge, *logit, *nsum, *gate, *gsum, *pool;
    __half *h0, *h1, *h2, *h3, *Ahf, *Bhf;
    unsigned *nmax, *gmax;
    cudaGetSymbolAddress((void**)&h0, g_h0);
    cudaGetSymbolAddress((void**)&h1, g_h1);
    cudaGetSymbolAddress((void**)&h2, g_h2);
    cudaGetSymbolAddress((void**)&h3, g_h3);
    cudaGetSymbolAddress((void**)&big2, g_big2);
    cudaGetSymbolAddress((void**)&Ahf, g_Ahf);
    cudaGetSymbolAddress((void**)&Bhf, g_Bhf);
    cudaGetSymbolAddress((void**)&P, g_P);
    cudaGetSymbolAddress((void**)&q3, g_q3);
    cudaGetSymbolAddress((void**)&ge, g_ge);
    cudaGetSymbolAddress((void**)&logit, g_logit);
    cudaGetSymbolAddress((void**)&nmax, g_nmax);
    cudaGetSymbolAddress((void**)&nsum, g_nsum);
    cudaGetSymbolAddress((void**)&gate, g_gate);
    cudaGetSymbolAddress((void**)&gmax, g_gmax);
    cudaGetSymbolAddress((void**)&gsum, g_gsum);
    cudaGetSymbolAddress((void**)&pool, g_pool);

    float* P1 = P;
    float* P2 = P + FF * FF;
    float* hq = q3;
    float* Gql = q3 + NB * FF;
    float* Gqr = q3 + 2 * NB * FF;

    cudaFuncSetAttribute(gemm_mega, cudaFuncAttributeMaxDynamicSharedMemorySize,
                         NSTAGE * GSTG);

    init_node_kernel<<<(NN + 255) / 256, 256>>>(nmax, nsum, gmax, gsum, pool);

    // ---- prep: fp16 entities ----
    cvtA_kernel<<<(NN * FF / 4 + 255) / 256, 256>>>((const float4*)entities,
                                                    (uint2*)Ahf, NN * FF / 4);

    // ---- P1 = inj_Wr @ enc_Wl, P2 = inj_Wr @ enc_Wr (fused split-K) ----
    zero_kernel<<<(2 * FF * FF / 4 + 255) / 256, 256>>>((float4*)P, 2 * FF * FF / 4);
    smallgemm2<<<dim3(2 * FF / 64, FF / SGK, FF / 64), 256>>>(inj_Wr, enc_Wl, enc_Wr,
                                                              P1, P2, FF, FF, FF);

    // ---- hq = queries@inj_Wr; then Gql/Gqr = hq@{enc_Wl,enc_Wr} (fused) ----
    zero_kernel<<<(3 * NB * FF / 4 + 255) / 256, 256>>>((float4*)q3, 3 * NB * FF / 4);
    smallgemm<<<dim3(FF / 64, FF / SGK, 1), 256>>>(queries, inj_Wr, hq, NB, FF, FF);
    smallgemm2<<<dim3(2 * FF / 64, FF / SGK, 1), 256>>>(hq, enc_Wl, enc_Wr, Gql, Gqr,
                                                        NB, FF, FF);

    // ---- ge = relations @ enc_We ----
    zero_kernel<<<(NRL * FF / 4 + 255) / 256, 256>>>((float4*)ge, NRL * FF / 4);
    smallgemm<<<dim3(FF / 64, FF / SGK, (NRL + 63) / 64), 256>>>(relations, enc_We, ge,
                                                                 NRL, FF, FF);

    // ---- fused mega weights [Wl | Wr | P1 | P2] -> Bhf fp16 ----
    wmegaT_kernel<<<dim3(FF / 32, NMEGA / 32), dim3(32, 8)>>>(inj_Wl, inj_Wr, P1, P2,
                                                              Bhf);

    // ---- mega GEMM: fp16(E) @ Bhf^T -> hl, hs, t1, t2 (fp16 outputs) ----
    gemm_mega<<<dim3(NMEGA / 128, (NN + 127) / 128), 128, NSTAGE * GSTG>>>(
        Ahf, Bhf, h0, h1, h2, h3, NN);

    // ---- injection attention + assembly -> fp16 gl/gr in-place (h2/h3) ----
    combine2_kernel<<<(NN * 32 + 255) / 256, 256>>>(h0, h1, h2, h3, hq, Gql, Gqr,
                                                    batch, inj_att);

    edge_logit_kernel<<<(NE * 32 + 255) / 256, 256>>>(h2, h3, ge, xcoo, enc_att,
                                                      logit);

    zero_kernel<<<(NN * FF / 4 + 255) / 256, 256>>>((float4*)big2, NN * FF / 4);

    edge_max_kernel<<<(NE + 255) / 256, 256>>>(xcoo, logit, nmax);
    edge_sum_kernel<<<(NE + 255) / 256, 256>>>(xcoo, logit, nmax, nsum);
    message_kernel<<<(NE * 32 + 255) / 256, 256>>>(xcoo, logit, nmax, nsum, h3, big2);

    node_post_kernel<<<(NN * 32 + 255) / 256, 256>>>(big2, gate_W, gate_b, gate);

    graph_max_kernel<<<(NN + 255) / 256, 256>>>(gate, batch, gmax);
    graph_sum_kernel<<<(NN + 255) / 256, 256>>>(gate, batch, gmax, gsum);
    gscale_kernel<<<(NN + 255) / 256, 256>>>(gate, batch, gsum);

    pool_kernel<<<dim3((NN + 1023) / 1024, 3), 256>>>(big2, gate, batch, pool);

    // out = pooled @ vt_W  [64,768]x[768,2304]
    zero_kernel<<<(NB * FV / 4 + 255) / 256, 256>>>((float4*)out, NB * FV / 4);
    smallgemm<<<dim3(FV / 64, FF / SGK, 1), 256>>>(pool, vt_W, out, NB, FV, FF);
}

// round 15
// speedup vs baseline: 1.6010x; 1.1098x over previous
#include <cuda_runtime.h>
#include <cuda_fp16.h>
#include <math.h>
#include <stdint.h>

#define NN 50000
#define NE 100000
#define NRL 500
#define NB 64
#define FF 768
#define FV 2304
#define NMEGA (4 * FF)  // 3072
#define ENC_NEG_INF 0x007FFFFFu

// ---------------- scratch (static device memory; no allocations) ------------
__device__ __align__(16) __half g_h0[NN * FF];    // hl -> msg accum / ent_emb (fp16)
__device__ __align__(16) __half g_h1[NN * FF];    // hs (fp16, GEMM out)
__device__ __align__(16) __half g_h2[NN * FF];    // t1 -> gl (fp16, in-place)
__device__ __align__(16) __half g_h3[NN * FF];    // t2 -> gr (fp16, in-place)
__device__ __align__(16) __half g_Ahf[NN * FF];   // fp16 entities
__device__ __align__(16) __half g_Bhf[NMEGA * FF];  // [3072,768] fused W^T fp16
__device__ __align__(16) float g_P[2 * FF * FF];  // P1 | P2
__device__ __align__(16) float g_q3[3 * NB * FF];  // hq | Gql | Gqr
__device__ __align__(16) float g_ge[NRL * FF];
__device__ float g_logit[NE];
__device__ unsigned g_nmax[NN];
__device__ float g_nsum[NN];
__device__ float g_gate[NN];
__device__ unsigned g_gmax[NB];
__device__ float g_gsum[NB];
__device__ __align__(16) float g_pool[NB * FF];

// ---------------- helpers ----------------------------------------------------
__device__ __forceinline__ float lrelu(float x) { return x > 0.f ? x : 0.2f * x; }

__device__ __forceinline__ unsigned f2ord(float f) {
    unsigned u = __float_as_uint(f);
    return (u & 0x80000000u) ? ~u : (u | 0x80000000u);
}
__device__ __forceinline__ float ord2f(unsigned u) {
    return (u & 0x80000000u) ? __uint_as_float(u & 0x7FFFFFFFu) : __uint_as_float(~u);
}

__device__ __forceinline__ unsigned cat_h(__half a, __half b) {
    return (unsigned)__half_as_ushort(a) | ((unsigned)__half_as_ushort(b) << 16);
}
__device__ __forceinline__ unsigned cat_f(float a, float b) {
    return cat_h(__float2half_rn(a), __float2half_rn(b));
}
__device__ __forceinline__ float2 h2f2(unsigned u) {
    __half2 h = *(__half2*)&u;
    return __half22float2(h);
}

__device__ __forceinline__ uint32_t smem_u32(const void* p) {
    uint32_t a;
    asm("{ .reg .u64 t; cvta.to.shared.u64 t, %1; cvt.u32.u64 %0, t; }" : "=r"(a) : "l"(p));
    return a;
}

__device__ __forceinline__ void ldsm4(unsigned* r, uint32_t addr) {
    asm volatile("ldmatrix.sync.aligned.m8n8.x4.shared.b16 {%0,%1,%2,%3}, [%4];"
                 : "=r"(r[0]), "=r"(r[1]), "=r"(r[2]), "=r"(r[3]) : "r"(addr));
}

__device__ __forceinline__ void mma_f16(float* d, const unsigned* a, unsigned b0,
                                        unsigned b1) {
    asm volatile(
        "mma.sync.aligned.m16n8k16.row.col.f32.f16.f16.f32 "
        "{%0,%1,%2,%3}, {%4,%5,%6,%7}, {%8,%9}, {%0,%1,%2,%3};"
        : "+f"(d[0]), "+f"(d[1]), "+f"(d[2]), "+f"(d[3])
        : "r"(a[0]), "r"(a[1]), "r"(a[2]), "r"(a[3]), "r"(b0), "r"(b1));
}

__device__ __forceinline__ void red_v4(float* p, float a, float b, float c, float d) {
    asm volatile("red.global.add.v4.f32 [%0], {%1,%2,%3,%4};"
                 :: "l"(p), "f"(a), "f"(b), "f"(c), "f"(d) : "memory");
}

__device__ __forceinline__ void red_h8(__half* p, unsigned a, unsigned b, unsigned c,
                                       unsigned d) {
    asm volatile("red.global.add.noftz.v4.f16x2 [%0], {%1,%2,%3,%4};"
                 :: "l"(p), "r"(a), "r"(b), "r"(c), "r"(d) : "memory");
}

// ---------------- fp16 mega GEMM (fp16 output) ----------------------------------
// Block 128x128, warp tile 64x64 (2x2 warps, 128 threads), BK=64, 3 stages,
// 2 CTAs/SM.
#define GRS 144
#define G_ATILE 18432
#define GSTG 36864
#define NSTAGE 3
#define NCHUNK 12

__global__ __launch_bounds__(128, 2)
void gemm_mega(const __half* __restrict__ Ah, const __half* __restrict__ Bh,
               __half* __restrict__ o0, __half* __restrict__ o1,
               __half* __restrict__ o2, __half* __restrict__ o3, int M) {
    extern __shared__ char smem[];
    const uint32_t sbase = smem_u32(smem);
    const int tid = threadIdx.x;
    const int lane = tid & 31;
    const int wid = tid >> 5;
    const int wm = wid >> 1;
    const int wn = wid & 1;
    const int m0 = blockIdx.y * 128;
    const int n0 = blockIdx.x * 128;

    auto load_stage = [&](int stg, int k0) {
        uint32_t sb = sbase + stg * GSTG;
#pragma unroll
        for (int t = 0; t < 16; t++) {
            int idx = tid + t * 128;
            int r = (idx >> 3) & 127;
            int c = idx & 7;
            uint32_t dst;
            const __half* g;
            int sz = 16;
            if (idx < 1024) {
                dst = sb + r * GRS + c * 16;
                int row = m0 + r;
                if (row >= M) { row = 0; sz = 0; }
                g = Ah + (size_t)row * FF + k0 + c * 8;
            } else {
                dst = sb + G_ATILE + r * GRS + c * 16;
                g = Bh + (size_t)(n0 + r) * FF + k0 + c * 8;
            }
            asm volatile("cp.async.cg.shared.global [%0], [%1], 16, %2;"
                         :: "r"(dst), "l"(g), "r"(sz));
        }
        asm volatile("cp.async.commit_group;" ::: "memory");
    };

    float acc[4][8][4];
#pragma unroll
    for (int i = 0; i < 4; i++)
#pragma unroll
        for (int t = 0; t < 8; t++)
#pragma unroll
            for (int q = 0; q < 4; q++) acc[i][t][q] = 0.f;

    const int fr = lane & 15;
    const int fko = (lane >> 4) * 16;

    load_stage(0, 0);
    load_stage(1, 64);

#pragma unroll 1
    for (int ch = 0; ch < NCHUNK; ch++) {
        if (ch < NCHUNK - 1)
            asm volatile("cp.async.wait_group 1;" ::: "memory");
        else
            asm volatile("cp.async.wait_group 0;" ::: "memory");
        __syncthreads();
        if (ch + 2 < NCHUNK) load_stage((ch + 2) % NSTAGE, (ch + 2) * 64);

        const uint32_t sb = sbase + (ch % NSTAGE) * GSTG;
#pragma unroll
        for (int ks = 0; ks < 4; ks++) {
            unsigned ah[4][4], bh[4][4];
            const uint32_t ko = (uint32_t)(ks * 32 + fko);
#pragma unroll
            for (int i = 0; i < 4; i++) {
                uint32_t ra = sb + (uint32_t)((wm * 64 + i * 16 + fr) * GRS) + ko;
                ldsm4(ah[i], ra);
            }
#pragma unroll
            for (int j = 0; j < 4; j++) {
                uint32_t rb = sb + G_ATILE + (uint32_t)((wn * 64 + j * 16 + fr) * GRS) + ko;
                ldsm4(bh[j], rb);
            }
#pragma unroll
            for (int i = 0; i < 4; i++) {
#pragma unroll
                for (int j = 0; j < 4; j++) {
#pragma unroll
                    for (int s = 0; s < 2; s++) {
                        mma_f16(acc[i][j * 2 + s], ah[i], bh[j][s], bh[j][s + 2]);
                    }
                }
            }
        }
        __syncthreads();
    }

    const int str = blockIdx.x / 6;
    __half* Cb = (str == 0) ? o0 : (str == 1) ? o1 : (str == 2) ? o2 : o3;
    const int nbase = (blockIdx.x % 6) * 128 + wn * 64;
#pragma unroll
    for (int i = 0; i < 4; i++) {
        const int r0 = m0 + wm * 64 + i * 16 + (lane >> 2);
#pragma unroll
        for (int t = 0; t < 8; t++) {
            const int col = nbase + t * 8 + (lane & 3) * 2;
            if (r0 < M)
                *(unsigned*)(Cb + (size_t)r0 * FF + col) =
                    cat_f(acc[i][t][0], acc[i][t][1]);
            if (r0 + 8 < M)
                *(unsigned*)(Cb + (size_t)(r0 + 8) * FF + col) =
                    cat_f(acc[i][t][2], acc[i][t][3]);
        }
    }
}

// ---------------- split-K small GEMM (dual output): shared A, two B/C ----------
#define SGK 128
__global__ __launch_bounds__(256) void smallgemm2(const float* __restrict__ A,
                                                  const float* __restrict__ B0,
                                                  const float* __restrict__ B1,
                                                  float* __restrict__ C0,
                                                  float* __restrict__ C1,
                                                  int M, int N, int K) {
    __shared__ float As[32][68];
    __shared__ float Bs[32][64];
    const int tid = threadIdx.x;
    const int nblk = N / 64;
    const int sel = blockIdx.x / nblk;
    const float* B = sel ? B1 : B0;
    float* C = sel ? C1 : C0;
    const int n0 = (blockIdx.x - sel * nblk) * 64;
    const int k0 = blockIdx.y * SGK;
    const int m0 = blockIdx.z * 64;
    const int tx = tid & 15, ty = tid >> 4;
    float acc[4][4] = {};

    for (int kt = 0; kt < SGK; kt += 32) {
        __syncthreads();
#pragma unroll
        for (int i = 0; i < 2; i++) {
            int idx = tid + i * 256;
            int r = idx >> 3, c = (idx & 7) * 4;
            float4 v = (m0 + r < M)
                           ? *(const float4*)(A + (size_t)(m0 + r) * K + k0 + kt + c)
                           : make_float4(0.f, 0.f, 0.f, 0.f);
            As[c + 0][r] = v.x;
            As[c + 1][r] = v.y;
            As[c + 2][r] = v.z;
            As[c + 3][r] = v.w;
            int rb = idx >> 4, cb = (idx & 15) * 4;
            *(float4*)&Bs[rb][cb] =
                *(const float4*)(B + (size_t)(k0 + kt + rb) * N + n0 + cb);
        }
        __syncthreads();
#pragma unroll
        for (int kk = 0; kk < 32; kk++) {
            float a0 = As[kk][ty * 4 + 0], a1 = As[kk][ty * 4 + 1];
            float a2 = As[kk][ty * 4 + 2], a3 = As[kk][ty * 4 + 3];
            float4 b = *(float4*)&Bs[kk][tx * 4];
            acc[0][0] += a0 * b.x; acc[0][1] += a0 * b.y; acc[0][2] += a0 * b.z; acc[0][3] += a0 * b.w;
            acc[1][0] += a1 * b.x; acc[1][1] += a1 * b.y; acc[1][2] += a1 * b.z; acc[1][3] += a1 * b.w;
            acc[2][0] += a2 * b.x; acc[2][1] += a2 * b.y; acc[2][2] += a2 * b.z; acc[2][3] += a2 * b.w;
            acc[3][0] += a3 * b.x; acc[3][1] += a3 * b.y; acc[3][2] += a3 * b.z; acc[3][3] += a3 * b.w;
        }
    }
#pragma unroll
    for (int i = 0; i < 4; i++) {
        int r = m0 + ty * 4 + i;
        if (r < M)
            red_v4(C + (size_t)r * N + n0 + tx * 4, acc[i][0], acc[i][1], acc[i][2],
                   acc[i][3]);
    }
}

// ---------------- split-K small GEMM (single) ------------------------------------
__global__ __launch_bounds__(256) void smallgemm(const float* __restrict__ A,
                                                 const float* __restrict__ B,
                                                 float* __restrict__ C,
                                                 int M, int N, int K) {
    __shared__ float As[32][68];
    __shared__ float Bs[32][64];
    const int tid = threadIdx.x;
    const int n0 = blockIdx.x * 64;
    const int k0 = blockIdx.y * SGK;
    const int m0 = blockIdx.z * 64;
    const int tx = tid & 15, ty = tid >> 4;
    float acc[4][4] = {};

    for (int kt = 0; kt < SGK; kt += 32) {
        __syncthreads();
#pragma unroll
        for (int i = 0; i < 2; i++) {
            int idx = tid + i * 256;
            int r = idx >> 3, c = (idx & 7) * 4;
            float4 v = (m0 + r < M)
                           ? *(const float4*)(A + (size_t)(m0 + r) * K + k0 + kt + c)
                           : make_float4(0.f, 0.f, 0.f, 0.f);
            As[c + 0][r] = v.x;
            As[c + 1][r] = v.y;
            As[c + 2][r] = v.z;
            As[c + 3][r] = v.w;
            int rb = idx >> 4, cb = (idx & 15) * 4;
            *(float4*)&Bs[rb][cb] =
                *(const float4*)(B + (size_t)(k0 + kt + rb) * N + n0 + cb);
        }
        __syncthreads();
#pragma unroll
        for (int kk = 0; kk < 32; kk++) {
            float a0 = As[kk][ty * 4 + 0], a1 = As[kk][ty * 4 + 1];
            float a2 = As[kk][ty * 4 + 2], a3 = As[kk][ty * 4 + 3];
            float4 b = *(float4*)&Bs[kk][tx * 4];
            acc[0][0] += a0 * b.x; acc[0][1] += a0 * b.y; acc[0][2] += a0 * b.z; acc[0][3] += a0 * b.w;
            acc[1][0] += a1 * b.x; acc[1][1] += a1 * b.y; acc[1][2] += a1 * b.z; acc[1][3] += a1 * b.w;
            acc[2][0] += a2 * b.x; acc[2][1] += a2 * b.y; acc[2][2] += a2 * b.z; acc[2][3] += a2 * b.w;
            acc[3][0] += a3 * b.x; acc[3][1] += a3 * b.y; acc[3][2] += a3 * b.z; acc[3][3] += a3 * b.w;
        }
    }
#pragma unroll
    for (int i = 0; i < 4; i++) {
        int r = m0 + ty * 4 + i;
        if (r < M)
            red_v4(C + (size_t)r * N + n0 + tx * 4, acc[i][0], acc[i][1], acc[i][2],
                   acc[i][3]);
    }
}

// ---------------- prep: fp32 -> fp16 convert ------------------------------------
__global__ void cvtA_kernel(const float4* __restrict__ in, uint2* __restrict__ hi,
                            int n4) {
    int i = blockIdx.x * blockDim.x + threadIdx.x;
    if (i >= n4) return;
    float4 v = in[i];
    hi[i] = make_uint2(cat_f(v.x, v.y), cat_f(v.z, v.w));
}

// ---------------- prep: transpose-cvt of 4 matrices (mega weights) -------------
__global__ void wmegaT_kernel(const float* __restrict__ Wl, const float* __restrict__ Wr,
                              const float* __restrict__ P1, const float* __restrict__ P2,
                              __half* __restrict__ Bh) {
    __shared__ float t[32][33];
    const int k0 = blockIdx.x * 32;
    const int n0g = blockIdx.y * 32;
    const int sel = n0g / FF;
    const float* W = (sel == 0) ? Wl : (sel == 1) ? Wr : (sel == 2) ? P1 : P2;
    const int n0 = n0g - sel * FF;
    const int tx = threadIdx.x, ty = threadIdx.y;
#pragma unroll
    for (int i = 0; i < 4; i++)
        t[ty + i * 8][tx] = W[(size_t)(k0 + ty + i * 8) * FF + n0 + tx];
    __syncthreads();
#pragma unroll
    for (int i = 0; i < 4; i++)
        Bh[(size_t)(n0g + ty + i * 8) * FF + k0 + tx] = __float2half_rn(t[tx][ty + i * 8]);
}

// ---------------- fused injection attention + encoder-input assembly ----------
__global__ void combine2_kernel(const __half* __restrict__ hl,
                                const __half* __restrict__ hs,
                                __half* __restrict__ t1,     // in: t1, out: gl
                                __half* __restrict__ t2,     // in: t2, out: gr
                                const float* __restrict__ hqg,
                                const float* __restrict__ Gql,
                                const float* __restrict__ Gqr,
                                const int* __restrict__ batch,
                                const float* __restrict__ att) {
    int warp = (blockIdx.x * blockDim.x + threadIdx.x) >> 5;
    int lane = threadIdx.x & 31;
    if (warp >= NN) return;
    const int b = batch[warp];
    const uint4* phl = (const uint4*)(hl + (size_t)warp * FF);
    const uint4* phs = (const uint4*)(hs + (size_t)warp * FF);
    const float4* phq = (const float4*)(hqg + (size_t)b * FF);
    const float4* pat = (const float4*)att;

    float sq = 0.f, ss = 0.f;
#pragma unroll
    for (int i = 0; i < 3; i++) {
        int j = lane + i * 32;
        uint4 l8 = phl[j], s8 = phs[j];
        float4 q0 = phq[j * 2], q1 = phq[j * 2 + 1];
        float4 a0 = pat[j * 2], a1 = pat[j * 2 + 1];
        float2 l0 = h2f2(l8.x), l1 = h2f2(l8.y), l2 = h2f2(l8.z), l3 = h2f2(l8.w);
        float2 s0 = h2f2(s8.x), s1 = h2f2(s8.y), s2 = h2f2(s8.z), s3 = h2f2(s8.w);
        sq += lrelu(l0.x + q0.x) * a0.x + lrelu(l0.y + q0.y) * a0.y +
              lrelu(l1.x + q0.z) * a0.z + lrelu(l1.y + q0.w) * a0.w +
              lrelu(l2.x + q1.x) * a1.x + lrelu(l2.y + q1.y) * a1.y +
              lrelu(l3.x + q1.z) * a1.z + lrelu(l3.y + q1.w) * a1.w;
        ss += lrelu(l0.x + s0.x) * a0.x + lrelu(l0.y + s0.y) * a0.y +
              lrelu(l1.x + s1.x) * a0.z + lrelu(l1.y + s1.y) * a0.w +
              lrelu(l2.x + s2.x) * a1.x + lrelu(l2.y + s2.y) * a1.y +
              lrelu(l3.x + s3.x) * a1.z + lrelu(l3.y + s3.y) * a1.w;
    }
#pragma unroll
    for (int o = 16; o > 0; o >>= 1) {
        sq += __shfl_xor_sync(0xFFFFFFFFu, sq, o);
        ss += __shfl_xor_sync(0xFFFFFFFFu, ss, o);
    }
    float m = fmaxf(sq, ss);
    float e0 = expf(sq - m), e1 = expf(ss - m);
    float inv = 1.f / (e0 + e1);
    float a0 = e0 * inv, a1 = e1 * inv;

    uint4* pt1 = (uint4*)(t1 + (size_t)warp * FF);
    uint4* pt2 = (uint4*)(t2 + (size_t)warp * FF);
    const float4* pgl = (const float4*)(Gql + (size_t)b * FF);
    const float4* pgr = (const float4*)(Gqr + (size_t)b * FF);
#pragma unroll
    for (int i = 0; i < 3; i++) {
        int j = lane + i * 32;
        uint4 u8 = pt1[j];
        float4 g0 = pgl[j * 2], g1 = pgl[j * 2 + 1];
        float2 u0 = h2f2(u8.x), u1 = h2f2(u8.y), u2 = h2f2(u8.z), u3 = h2f2(u8.w);
        uint4 og;
        og.x = cat_f(a0 * g0.x + a1 * u0.x, a0 * g0.y + a1 * u0.y);
        og.y = cat_f(a0 * g0.z + a1 * u1.x, a0 * g0.w + a1 * u1.y);
        og.z = cat_f(a0 * g1.x + a1 * u2.x, a0 * g1.y + a1 * u2.y);
        og.w = cat_f(a0 * g1.z + a1 * u3.x, a0 * g1.w + a1 * u3.y);
        pt1[j] = og;
        uint4 v8 = pt2[j];
        float4 h0 = pgr[j * 2], h1 = pgr[j * 2 + 1];
        float2 v0 = h2f2(v8.x), v1 = h2f2(v8.y), v2 = h2f2(v8.z), v3 = h2f2(v8.w);
        uint4 orr;
        orr.x = cat_f(a0 * h0.x + a1 * v0.x, a0 * h0.y + a1 * v0.y);
        orr.y = cat_f(a0 * h0.z + a1 * v1.x, a0 * h0.w + a1 * v1.y);
        orr.z = cat_f(a0 * h1.x + a1 * v2.x, a0 * h1.y + a1 * v2.y);
        orr.w = cat_f(a0 * h1.z + a1 * v3.x, a0 * h1.w + a1 * v3.y);
        pt2[j] = orr;
    }
}

// ---------------- edge logits (one warp per edge, fp16 gathers) ----------------
__global__ void edge_logit_kernel(const __half* __restrict__ glh,
                                  const __half* __restrict__ grh,
                                  const float* __restrict__ ge,
                                  const int* __restrict__ xcoo,
                                  const float* __restrict__ att,
                                  float* __restrict__ logit) {
    int warp = (blockIdx.x * blockDim.x + threadIdx.x) >> 5;
    int lane = threadIdx.x & 31;
    if (warp >= NE) return;
    int src = xcoo[warp * 3 + 0];
    int rel = xcoo[warp * 3 + 1];
    int tgt = xcoo[warp * 3 + 2];
    const uint4* pt = (const uint4*)(glh + (size_t)tgt * FF);
    const uint4* pr = (const uint4*)(grh + (size_t)src * FF);
    const float4* pe = (const float4*)(ge + (size_t)rel * FF);
    const float4* pa = (const float4*)att;
    float s = 0.f;
#pragma unroll
    for (int i = 0; i < 3; i++) {
        int j = lane + i * 32;
        uint4 t8 = pt[j], r8 = pr[j];
        float4 e0 = pe[j * 2], e1 = pe[j * 2 + 1];
        float4 a0 = pa[j * 2], a1 = pa[j * 2 + 1];
        float2 t0 = h2f2(t8.x), t1 = h2f2(t8.y), t2 = h2f2(t8.z), t3 = h2f2(t8.w);
        float2 r0 = h2f2(r8.x), r1 = h2f2(r8.y), r2 = h2f2(r8.z), r3 = h2f2(r8.w);
        s += lrelu(t0.x + r0.x + e0.x) * a0.x + lrelu(t0.y + r0.y + e0.y) * a0.y +
             lrelu(t1.x + r1.x + e0.z) * a0.z + lrelu(t1.y + r1.y + e0.w) * a0.w +
             lrelu(t2.x + r2.x + e1.x) * a1.x + lrelu(t2.y + r2.y + e1.y) * a1.y +
             lrelu(t3.x + r3.x + e1.z) * a1.z + lrelu(t3.y + r3.y + e1.w) * a1.w;
    }
#pragma unroll
    for (int o = 16; o > 0; o >>= 1) s += __shfl_xor_sync(0xFFFFFFFFu, s, o);
    if (lane == 0) logit[warp] = s;
}

// ---------------- segment softmax over edges (tgt) ----------------------------
__global__ void edge_max_kernel(const int* __restrict__ xcoo,
                                const float* __restrict__ logit,
                                unsigned* __restrict__ nmax) {
    int e = blockIdx.x * blockDim.x + threadIdx.x;
    if (e < NE) atomicMax(&nmax[xcoo[e * 3 + 2]], f2ord(logit[e]));
}

__global__ void edge_sum_kernel(const int* __restrict__ xcoo,
                                const float* __restrict__ logit,
                                const unsigned* __restrict__ nmax,
                                float* __restrict__ nsum) {
    int e = blockIdx.x * blockDim.x + threadIdx.x;
    if (e < NE) {
        int t = xcoo[e * 3 + 2];
        atomicAdd(&nsum[t], expf(logit[e] - ord2f(nmax[t])));
    }
}

// ---------------- message scatter (fp16 gather, fp16x2 red accumulate) ---------
__global__ void message_kernel(const int* __restrict__ xcoo,
                               const float* __restrict__ logit,
                               const unsigned* __restrict__ nmax,
                               const float* __restrict__ nsum,
                               const __half* __restrict__ grh,
                               __half* __restrict__ acc) {
    int warp = (blockIdx.x * blockDim.x + threadIdx.x) >> 5;
    int lane = threadIdx.x & 31;
    if (warp >= NE) return;
    int src = xcoo[warp * 3 + 0];
    int tgt = xcoo[warp * 3 + 2];
    float alpha = expf(logit[warp] - ord2f(nmax[tgt])) / (nsum[tgt] + 1e-16f);
    const uint4* pr = (const uint4*)(grh + (size_t)src * FF);
    __half* pd = acc + (size_t)tgt * FF;
#pragma unroll
    for (int i = 0; i < 3; i++) {
        int j = lane + i * 32;
        uint4 v = pr[j];
        float2 f0 = h2f2(v.x), f1 = h2f2(v.y), f2 = h2f2(v.z), f3 = h2f2(v.w);
        red_h8(pd + j * 8, cat_f(alpha * f0.x, alpha * f0.y),
               cat_f(alpha * f1.x, alpha * f1.y), cat_f(alpha * f2.x, alpha * f2.y),
               cat_f(alpha * f3.x, alpha * f3.y));
    }
}

// ---------------- elu + gate dot (fp16 in/out, one warp per node) --------------
__global__ void node_post_kernel(__half* __restrict__ emb,
                                 const float* __restrict__ gate_W,
                                 const float* __restrict__ gate_b,
                                 float* __restrict__ gate) {
    int warp = (blockIdx.x * blockDim.x + threadIdx.x) >> 5;
    int lane = threadIdx.x & 31;
    if (warp >= NN) return;
    uint4* p = (uint4*)(emb + (size_t)warp * FF);
    const float4* pw = (const float4*)gate_W;
    float s = 0.f;
#pragma unroll
    for (int i = 0; i < 3; i++) {
        int j = lane + i * 32;
        uint4 v8 = p[j];
        float2 v0 = h2f2(v8.x), v1 = h2f2(v8.y), v2 = h2f2(v8.z), v3 = h2f2(v8.w);
        float e[8];
        e[0] = v0.x > 0.f ? v0.x : expm1f(v0.x);
        e[1] = v0.y > 0.f ? v0.y : expm1f(v0.y);
        e[2] = v1.x > 0.f ? v1.x : expm1f(v1.x);
        e[3] = v1.y > 0.f ? v1.y : expm1f(v1.y);
        e[4] = v2.x > 0.f ? v2.x : expm1f(v2.x);
        e[5] = v2.y > 0.f ? v2.y : expm1f(v2.y);
        e[6] = v3.x > 0.f ? v3.x : expm1f(v3.x);
        e[7] = v3.y > 0.f ? v3.y : expm1f(v3.y);
        uint4 o;
        o.x = cat_f(e[0], e[1]);
        o.y = cat_f(e[2], e[3]);
        o.z = cat_f(e[4], e[5]);
        o.w = cat_f(e[6], e[7]);
        p[j] = o;
        float4 w0 = pw[j * 2], w1 = pw[j * 2 + 1];
        s += e[0] * w0.x + e[1] * w0.y + e[2] * w0.z + e[3] * w0.w +
             e[4] * w1.x + e[5] * w1.y + e[6] * w1.z + e[7] * w1.w;
    }
#pragma unroll
    for (int o = 16; o > 0; o >>= 1) s += __shfl_xor_sync(0xFFFFFFFFu, s, o);
    if (lane == 0) gate[warp] = s + gate_b[0];
}

// ---------------- graph softmax over nodes ------------------------------------
__global__ void graph_max_kernel(const float* __restrict__ gate,
                                 const int* __restrict__ batch,
                                 unsigned* __restrict__ gmax) {
    int n = blockIdx.x * blockDim.x + threadIdx.x;
    if (n < NN) atomicMax(&gmax[batch[n]], f2ord(gate[n]));
}

__global__ void graph_sum_kernel(float* __restrict__ gate,
                                 const int* __restrict__ batch,
                                 const unsigned* __restrict__ gmax,
                                 float* __restrict__ gsum) {
    int n = blockIdx.x * blockDim.x + threadIdx.x;
    if (n < NN) {
        float ex = expf(gate[n] - ord2f(gmax[batch[n]]));
        gate[n] = ex;
        atomicAdd(&gsum[batch[n]], ex);
    }
}

__global__ void gscale_kernel(float* __restrict__ gate,
                              const int* __restrict__ batch,
                              const float* __restrict__ gsum) {
    int n = blockIdx.x * blockDim.x + threadIdx.x;
    if (n < NN) gate[n] = gate[n] / (gsum[batch[n]] + 1e-16f);
}

// ---------------- pooled = segment_sum(g * emb, batch) (fp16 emb, sorted) -----
__global__ void pool_kernel(const __half* __restrict__ emb,
                            const float* __restrict__ g,
                            const int* __restrict__ batch,
                            float* __restrict__ pool) {
    int f = blockIdx.y * 256 + threadIdx.x;
    int n0 = blockIdx.x * 1024;
    int n1 = min(n0 + 1024, NN);
    float acc = 0.f;
    int curb = batch[n0];
    for (int n = n0; n < n1; n++) {
        int b = batch[n];
        if (b != curb) {
            atomicAdd(&pool[(size_t)curb * FF + f], acc);
            acc = 0.f;
            curb = b;
        }
        acc += g[n] * __half2float(emb[(size_t)n * FF + f]);
    }
    atomicAdd(&pool[(size_t)curb * FF + f], acc);
}

// ---------------- init kernels --------------------------------------------------
__global__ void init_node_kernel(unsigned* nmax, float* nsum, unsigned* gmax,
                                 float* gsum, float* pool) {
    int i = blockIdx.x * blockDim.x + threadIdx.x;
    if (i < NN) {
        nmax[i] = ENC_NEG_INF;
        nsum[i] = 0.f;
    }
    if (i < NB) {
        gmax[i] = ENC_NEG_INF;
        gsum[i] = 0.f;
    }
    if (i < NB * FF) pool[i] = 0.f;
}

__global__ void zero_kernel(float4* p, int n4) {
    int i = blockIdx.x * blockDim.x + threadIdx.x;
    if (i < n4) p[i] = make_float4(0.f, 0.f, 0.f, 0.f);
}

// ---------------- launcher -------------------------------------------------------
extern "C" void kernel_launch(void* const* d_in, const int* in_sizes, int n_in,
                              void* d_out, int out_size) {
    const float* queries = (const float*)d_in[0];
    const float* entities = (const float*)d_in[1];
    const float* relations = (const float*)d_in[2];
    const int* xcoo = (const int*)d_in[3];
    const int* batch = (const int*)d_in[4];
    const float* inj_Wl = (const float*)d_in[5];
    const float* inj_Wr = (const float*)d_in[6];
    const float* inj_att = (const float*)d_in[7];
    const float* enc_Wl = (const float*)d_in[8];
    const float* enc_Wr = (const float*)d_in[9];
    const float* enc_We = (const float*)d_in[10];
    const float* enc_att = (const float*)d_in[11];
    /* d_in[12] enc_Wrel: dead code in reference */
    const float* gate_W = (const float*)d_in[13];
    const float* gate_b = (const float*)d_in[14];
    const float* vt_W = (const float*)d_in[15];
    float* out = (float*)d_out;

    float *P, *q3, *ge, *logit, *nsum, *gate, *gsum, *pool;
    __half *h0, *h1, *h2, *h3, *Ahf, *Bhf;
    unsigned *nmax, *gmax;
    cudaGetSymbolAddress((void**)&h0, g_h0);
    cudaGetSymbolAddress((void**)&h1, g_h1);
    cudaGetSymbolAddress((void**)&h2, g_h2);
    cudaGetSymbolAddress((void**)&h3, g_h3);
    cudaGetSymbolAddress((void**)&Ahf, g_Ahf);
    cudaGetSymbolAddress((void**)&Bhf, g_Bhf);
    cudaGetSymbolAddress((void**)&P, g_P);
    cudaGetSymbolAddress((void**)&q3, g_q3);
    cudaGetSymbolAddress((void**)&ge, g_ge);
    cudaGetSymbolAddress((void**)&logit, g_logit);
    cudaGetSymbolAddress((void**)&nmax, g_nmax);
    cudaGetSymbolAddress((void**)&nsum, g_nsum);
    cudaGetSymbolAddress((void**)&gate, g_gate);
    cudaGetSymbolAddress((void**)&gmax, g_gmax);
    cudaGetSymbolAddress((void**)&gsum, g_gsum);
    cudaGetSymbolAddress((void**)&pool, g_pool);

    float* P1 = P;
    float* P2 = P + FF * FF;
    float* hq = q3;
    float* Gql = q3 + NB * FF;
    float* Gqr = q3 + 2 * NB * FF;

    cudaFuncSetAttribute(gemm_mega, cudaFuncAttributeMaxDynamicSharedMemorySize,
                         NSTAGE * GSTG);

    init_node_kernel<<<(NN + 255) / 256, 256>>>(nmax, nsum, gmax, gsum, pool);

    // ---- prep: fp16 entities ----
    cvtA_kernel<<<(NN * FF / 4 + 255) / 256, 256>>>((const float4*)entities,
                                                    (uint2*)Ahf, NN * FF / 4);

    // ---- P1 = inj_Wr @ enc_Wl, P2 = inj_Wr @ enc_Wr (fused split-K) ----
    zero_kernel<<<(2 * FF * FF / 4 + 255) / 256, 256>>>((float4*)P, 2 * FF * FF / 4);
    smallgemm2<<<dim3(2 * FF / 64, FF / SGK, FF / 64), 256>>>(inj_Wr, enc_Wl, enc_Wr,
                                                              P1, P2, FF, FF, FF);

    // ---- hq = queries@inj_Wr; then Gql/Gqr = hq@{enc_Wl,enc_Wr} (fused) ----
    zero_kernel<<<(3 * NB * FF / 4 + 255) / 256, 256>>>((float4*)q3, 3 * NB * FF / 4);
    smallgemm<<<dim3(FF / 64, FF / SGK, 1), 256>>>(queries, inj_Wr, hq, NB, FF, FF);
    smallgemm2<<<dim3(2 * FF / 64, FF / SGK, 1), 256>>>(hq, enc_Wl, enc_Wr, Gql, Gqr,
                                                        NB, FF, FF);

    // ---- ge = relations @ enc_We ----
    zero_kernel<<<(NRL * FF / 4 + 255) / 256, 256>>>((float4*)ge, NRL * FF / 4);
    smallgemm<<<dim3(FF / 64, FF / SGK, (NRL + 63) / 64), 256>>>(relations, enc_We, ge,
                                                                 NRL, FF, FF);

    // ---- fused mega weights [Wl | Wr | P1 | P2] -> Bhf fp16 ----
    wmegaT_kernel<<<dim3(FF / 32, NMEGA / 32), dim3(32, 8)>>>(inj_Wl, inj_Wr, P1, P2,
                                                              Bhf);

    // ---- mega GEMM: fp16(E) @ Bhf^T -> hl, hs, t1, t2 (fp16 outputs) ----
    gemm_mega<<<dim3(NMEGA / 128, (NN + 127) / 128), 128, NSTAGE * GSTG>>>(
        Ahf, Bhf, h0, h1, h2, h3, NN);

    // ---- injection attention + assembly -> fp16 gl/gr in-place (h2/h3) ----
    combine2_kernel<<<(NN * 32 + 255) / 256, 256>>>(h0, h1, h2, h3, hq, Gql, Gqr,
                                                    batch, inj_att);

    edge_logit_kernel<<<(NE * 32 + 255) / 256, 256>>>(h2, h3, ge, xcoo, enc_att,
                                                      logit);

    // h0 free after combine2 -> becomes fp16 message accumulator
    zero_kernel<<<(NN * FF / 8 + 255) / 256, 256>>>((float4*)h0, NN * FF / 8);

    edge_max_kernel<<<(NE + 255) / 256, 256>>>(xcoo, logit, nmax);
    edge_sum_kernel<<<(NE + 255) / 256, 256>>>(xcoo, logit, nmax, nsum);
    message_kernel<<<(NE * 32 + 255) / 256, 256>>>(xcoo, logit, nmax, nsum, h3, h0);

    node_post_kernel<<<(NN * 32 + 255) / 256, 256>>>(h0, gate_W, gate_b, gate);

    graph_max_kernel<<<(NN + 255) / 256, 256>>>(gate, batch, gmax);
    graph_sum_kernel<<<(NN + 255) / 256, 256>>>(gate, batch, gmax, gsum);
    gscale_kernel<<<(NN + 255) / 256, 256>>>(gate, batch, gsum);

    pool_kernel<<<dim3((NN + 1023) / 1024, 3), 256>>>(h0, gate, batch, pool);

    // out = pooled @ vt_W  [64,768]x[768,2304]
    zero_kernel<<<(NB * FV / 4 + 255) / 256, 256>>>((float4*)out, NB * FV / 4);
    smallgemm<<<dim3(FV / 64, FF / SGK, 1), 256>>>(pool, vt_W, out, NB, FV, FF);
}